// round 1
// baseline (speedup 1.0000x reference)
#include <cuda_runtime.h>

#define LLEN 1024
#define DD   128
#define EPSF 1e-5f
#define NMT  8      // m-tiles (of 16 m) per CTA in cop_kernel

// ---------------- scratch (device globals; no allocation) ----------------
__device__ float g_a   [LLEN * DD];        // a  = x @ Wl.T  + bl
__device__ float g_tx  [LLEN * DD];        // tx = x @ Wl2.T + bl2
__device__ float g_wloT[DD * DD];          // Wlo transposed: wloT[c][d] = Wlo[d][c]
__device__ float g_part[NMT * LLEN * DD];  // deterministic partial sums over m-groups

// ---------------- kernel 1: a and tx projections ----------------
__global__ __launch_bounds__(256) void proj_kernel(
    const float* __restrict__ x,
    const float* __restrict__ Wl,  const float* __restrict__ bl,
    const float* __restrict__ Wl2, const float* __restrict__ bl2)
{
    __shared__ float xs[8 * DD];
    __shared__ float ws[32 * 129];   // padded rows to kill bank conflicts
    const int t    = threadIdx.x;
    const int l0   = blockIdx.x * 8;
    const int dloc = t & 31;
    const int lrow = t >> 5;

    for (int i = t; i < 8 * DD; i += 256) xs[i] = x[l0 * DD + i];

    for (int mat = 0; mat < 2; mat++) {
        const float* W    = mat ? Wl2 : Wl;
        const float* bias = mat ? bl2 : bl;
        float*       out  = mat ? g_tx : g_a;
        for (int dc = 0; dc < 4; dc++) {
            const int d0 = dc * 32;
            __syncthreads();                       // covers xs (iter 0) / prev compute
            for (int i = t; i < 32 * DD; i += 256) {
                int r = i >> 7, c = i & 127;
                ws[r * 129 + c] = W[(d0 + r) * DD + c];
            }
            __syncthreads();
            float acc = 0.f;
            #pragma unroll 8
            for (int c = 0; c < DD; c++)
                acc += xs[lrow * DD + c] * ws[dloc * 129 + c];
            out[(l0 + lrow) * DD + d0 + dloc] = acc + bias[d0 + dloc];
        }
    }
}

// ---------------- kernel 2: transpose Wlo ----------------
__global__ void transpose_kernel(const float* __restrict__ Wlo)
{
    int i = blockIdx.x * 256 + threadIdx.x;   // 0..16383
    int r = i >> 7, c = i & 127;
    g_wloT[c * DD + r] = Wlo[i];
}

// ---------------- kernel 3: the fused pair-GEMM + mask + contraction ----------------
// out1[l,d] partials: for pairs (l in 8-tile, m in 16-tile):
//   P[l,m,d] = sum_c a[l,c]*a[m,c]*Wlo[d,c]
//   s[l,d]  += mask[l,m] * (P + blo[d]) * tx[m,d]
__global__ __launch_bounds__(256, 2) void cop_kernel(
    const int*   __restrict__ mask,
    const float* __restrict__ blo)
{
    __shared__ float s_al [8  * DD];
    __shared__ float s_am [16 * 129];   // padded (half-warp reads 2 distinct rows)
    __shared__ float s_tx [16 * DD];
    __shared__ float s_b  [32 * DD];    // Wlo^T k-chunk: s_b[cc][d]
    __shared__ float s_blo[DD];
    __shared__ int   s_mask[8 * 16];
    __shared__ float s_red[8 * DD];

    const int t   = threadIdx.x;
    const int txi = t & 15;         // d-group
    const int tyi = t >> 4;         // row-group
    const int li  = tyi >> 1;       // 0..7   (l within tile)
    const int mi0 = (tyi & 1) * 8;  // 0 or 8 (m half)
    const int d0  = txi * 8;

    const int lt = blockIdx.y;      // 0..127
    const int mg = blockIdx.x;      // 0..7
    const int l0 = lt * 8;

    // a_l rows + blo (once)
    {
        float4*       dst = (float4*)s_al;
        const float4* src = (const float4*)(g_a + l0 * DD);
        dst[t] = src[t];
    }
    if (t < DD) s_blo[t] = blo[t];

    float s[8];
    #pragma unroll
    for (int q = 0; q < 8; q++) s[q] = 0.f;

    #pragma unroll 1
    for (int mtl = 0; mtl < NMT; mtl++) {
        const int m0 = (mg * NMT + mtl) * 16;
        __syncthreads();   // protect s_am/s_tx/s_mask reuse across m-tiles
        // load a_m (padded rows) and tx_m
        for (int i = t; i < 16 * DD; i += 256) {
            int r = i >> 7, c = i & 127;
            s_am[r * 129 + c] = g_a[(m0 + r) * DD + c];
        }
        {
            float4*       tx4 = (float4*)s_tx;
            const float4* gt  = (const float4*)(g_tx + m0 * DD);
            tx4[t] = gt[t]; tx4[t + 256] = gt[t + 256];
        }
        if (t < 128) s_mask[t] = mask[(l0 + (t >> 4)) * LLEN + m0 + (t & 15)];

        unsigned long long acc[8][4];   // packed f32x2 accumulators: 8 rows x 8 d
        #pragma unroll
        for (int j = 0; j < 8; j++)
            #pragma unroll
            for (int q = 0; q < 4; q++) acc[j][q] = 0ull;

        #pragma unroll 1
        for (int kc = 0; kc < 4; kc++) {
            __syncthreads();
            {   // B chunk: wloT rows kc*32..kc*32+31
                float4*       b4 = (float4*)s_b;
                const float4* gb = (const float4*)(g_wloT + kc * 32 * DD);
                #pragma unroll
                for (int r = 0; r < 4; r++) b4[t + r * 256] = gb[t + r * 256];
            }
            __syncthreads();
            const float* alp = s_al + li * DD + kc * 32;
            const float* amp = s_am + mi0 * 129 + kc * 32;
            #pragma unroll 4
            for (int cc = 0; cc < 32; cc++) {
                const float al = alp[cc];
                const ulonglong2* bp = (const ulonglong2*)&s_b[cc * DD + d0];
                const ulonglong2 b01 = bp[0];
                const ulonglong2 b23 = bp[1];
                #pragma unroll
                for (int j = 0; j < 8; j++) {
                    float e = al * amp[j * 129 + cc];
                    unsigned long long ee;
                    asm("mov.b64 %0, {%1, %1};" : "=l"(ee) : "f"(e));
                    asm("fma.rn.f32x2 %0, %1, %2, %0;" : "+l"(acc[j][0]) : "l"(ee), "l"(b01.x));
                    asm("fma.rn.f32x2 %0, %1, %2, %0;" : "+l"(acc[j][1]) : "l"(ee), "l"(b01.y));
                    asm("fma.rn.f32x2 %0, %1, %2, %0;" : "+l"(acc[j][2]) : "l"(ee), "l"(b23.x));
                    asm("fma.rn.f32x2 %0, %1, %2, %0;" : "+l"(acc[j][3]) : "l"(ee), "l"(b23.y));
                }
            }
        }

        // epilogue for this m-tile: mask * (P + blo) * tx, accumulate into s
        #pragma unroll
        for (int j = 0; j < 8; j++) {
            if (s_mask[li * 16 + mi0 + j]) {
                const float* txr = s_tx + (mi0 + j) * DD + d0;
                #pragma unroll
                for (int q = 0; q < 4; q++) {
                    float lo, hi;
                    asm("mov.b64 {%0, %1}, %2;" : "=f"(lo), "=f"(hi) : "l"(acc[j][q]));
                    s[2*q]   += (lo + s_blo[d0 + 2*q])   * txr[2*q];
                    s[2*q+1] += (hi + s_blo[d0 + 2*q+1]) * txr[2*q+1];
                }
            }
        }
    }

    // partner reduction (two m-halves share (li, d0)) then deterministic partial write
    __syncthreads();
    if (tyi & 1) {
        #pragma unroll
        for (int q = 0; q < 8; q++) s_red[li * DD + d0 + q] = s[q];
    }
    __syncthreads();
    if (!(tyi & 1)) {
        const int l = l0 + li;
        #pragma unroll
        for (int q = 0; q < 8; q++)
            g_part[(mg * LLEN + l) * DD + d0 + q] = s[q] + s_red[li * DD + d0 + q];
    }
}

// ---------------- kernel 4: residual + partial reduce + LayerNorm ----------------
__global__ __launch_bounds__(128) void ln_kernel(
    const float* __restrict__ x,
    const float* __restrict__ gamma, const float* __restrict__ beta,
    float* __restrict__ out)
{
    __shared__ float w1[4], w2[4];
    __shared__ float mu_s, rstd_s;
    const int l = blockIdx.x;
    const int d = threadIdx.x;

    float y = x[l * DD + d];
    #pragma unroll
    for (int p = 0; p < NMT; p++) y += g_part[(p * LLEN + l) * DD + d];

    float s1 = y, s2 = y * y;
    #pragma unroll
    for (int off = 16; off > 0; off >>= 1) {
        s1 += __shfl_down_sync(0xffffffffu, s1, off);
        s2 += __shfl_down_sync(0xffffffffu, s2, off);
    }
    const int wid = d >> 5, lid = d & 31;
    if (lid == 0) { w1[wid] = s1; w2[wid] = s2; }
    __syncthreads();
    if (d == 0) {
        float t1 = w1[0] + w1[1] + w1[2] + w1[3];
        float t2 = w2[0] + w2[1] + w2[2] + w2[3];
        float mu = t1 * (1.f / DD);
        float var = t2 * (1.f / DD) - mu * mu;
        mu_s = mu; rstd_s = rsqrtf(var + EPSF);
    }
    __syncthreads();
    out[l * DD + d] = (y - mu_s) * rstd_s * gamma[d] + beta[d];
}

// ---------------- launch ----------------
extern "C" void kernel_launch(void* const* d_in, const int* in_sizes, int n_in,
                              void* d_out, int out_size)
{
    (void)in_sizes; (void)n_in; (void)out_size;
    const float* x     = (const float*)d_in[0];
    const int*   mask  = (const int*)  d_in[1];
    const float* Wl    = (const float*)d_in[2];
    const float* bl    = (const float*)d_in[3];
    const float* Wlo   = (const float*)d_in[4];
    const float* blo   = (const float*)d_in[5];
    const float* Wl2   = (const float*)d_in[6];
    const float* bl2   = (const float*)d_in[7];
    const float* gamma = (const float*)d_in[8];
    const float* beta  = (const float*)d_in[9];
    float* out = (float*)d_out;

    proj_kernel<<<128, 256>>>(x, Wl, bl, Wl2, bl2);
    transpose_kernel<<<64, 256>>>(Wlo);
    cop_kernel<<<dim3(8, 128), 256>>>(mask, blo);
    ln_kernel<<<1024, 128>>>(x, gamma, beta, out);
}

// round 3
// speedup vs baseline: 2.3332x; 2.3332x over previous
#include <cuda_runtime.h>
#include <cuda_bf16.h>

#define LLEN 1024
#define DD   128
#define EPSF 1e-5f
#define LP   4

// ---------------- scratch (device globals; no allocation) ----------------
__device__ float g_a [LLEN * DD];   // a  = x @ Wl.T  + bl
__device__ float g_tx[LLEN * DD];   // tx = x @ Wl2.T + bl2
__device__ float g_R [LLEN * DD];   // R[l,d] = sum_m mask[l,m] * tx[m,d]
__device__ float g_o1[LLEN * DD];   // out1[l,d] (pre-residual, pre-LN)

// ---------------- helpers ----------------
__device__ __forceinline__ unsigned pack_bf16x2(float lo, float hi) {
    unsigned u;
    asm("cvt.rn.bf16x2.f32 %0, %1, %2;" : "=r"(u) : "f"(hi), "f"(lo));
    return u;
}
__device__ __forceinline__ void split_bf16(float x0, float x1, unsigned& uh, unsigned& um) {
    uh = pack_bf16x2(x0, x1);
    float h0 = __uint_as_float(uh << 16);
    float h1 = __uint_as_float(uh & 0xFFFF0000u);
    um = pack_bf16x2(x0 - h0, x1 - h1);
}
__device__ __forceinline__ void mma_bf16(float* c, unsigned a0, unsigned a1, unsigned a2,
                                         unsigned a3, unsigned b0, unsigned b1) {
    asm volatile(
        "mma.sync.aligned.m16n8k16.row.col.f32.bf16.bf16.f32 "
        "{%0,%1,%2,%3}, {%4,%5,%6,%7}, {%8,%9}, {%0,%1,%2,%3};"
        : "+f"(c[0]), "+f"(c[1]), "+f"(c[2]), "+f"(c[3])
        : "r"(a0), "r"(a1), "r"(a2), "r"(a3), "r"(b0), "r"(b1));
}

// ---------------- kernel 1: projections (verified in R1) ----------------
__global__ __launch_bounds__(256) void proj_kernel(
    const float* __restrict__ x,
    const float* __restrict__ Wl,  const float* __restrict__ bl,
    const float* __restrict__ Wl2, const float* __restrict__ bl2)
{
    __shared__ float xs[8 * DD];
    __shared__ float ws[32 * 129];
    const int t = threadIdx.x, l0 = blockIdx.x * 8;
    const int dloc = t & 31, lrow = t >> 5;
    for (int i = t; i < 8 * DD; i += 256) xs[i] = x[l0 * DD + i];
    for (int mat = 0; mat < 2; mat++) {
        const float* W    = mat ? Wl2 : Wl;
        const float* bias = mat ? bl2 : bl;
        float*       outp = mat ? g_tx : g_a;
        for (int dc = 0; dc < 4; dc++) {
            const int d0 = dc * 32;
            __syncthreads();
            for (int i = t; i < 32 * DD; i += 256) {
                int r = i >> 7, c = i & 127;
                ws[r * 129 + c] = W[(d0 + r) * DD + c];
            }
            __syncthreads();
            float acc = 0.f;
            #pragma unroll 8
            for (int c = 0; c < DD; c++) acc += xs[lrow * DD + c] * ws[dloc * 129 + c];
            outp[(l0 + lrow) * DD + d0 + dloc] = acc + bias[d0 + dloc];
        }
    }
}

// ---------------- kernel 2: R[l,d] = sum_m mask[l,m]*tx[m,d] ----------------
__global__ __launch_bounds__(256) void r_kernel(const int* __restrict__ mask)
{
    __shared__ float s_txc[64 * DD];
    __shared__ float s_mk [16 * 64];
    const int t = threadIdx.x;
    const int l0 = blockIdx.x * 16;
    const int d4 = t & 31, lg = t >> 5;
    float4 a0 = {0.f,0.f,0.f,0.f}, a1 = {0.f,0.f,0.f,0.f};
    for (int ch = 0; ch < 16; ch++) {
        const int m0 = ch * 64;
        __syncthreads();
        #pragma unroll
        for (int r = 0; r < 8; r++) {
            int idx = t + 256 * r;
            int rw = idx >> 5, c4 = idx & 31;
            *(float4*)&s_txc[rw * DD + c4 * 4] = *(const float4*)&g_tx[(m0 + rw) * DD + c4 * 4];
        }
        #pragma unroll
        for (int r = 0; r < 4; r++) {
            int idx = t + 256 * r;
            int li = idx >> 6, mm = idx & 63;
            s_mk[li * 64 + mm] = (mask[(l0 + li) * LLEN + m0 + mm] != 0) ? 1.f : 0.f;
        }
        __syncthreads();
        #pragma unroll 4
        for (int mm = 0; mm < 64; mm++) {
            float4 tv = *(float4*)&s_txc[mm * DD + d4 * 4];
            float f0 = s_mk[(lg * 2) * 64 + mm];
            float f1 = s_mk[(lg * 2 + 1) * 64 + mm];
            a0.x += tv.x * f0; a0.y += tv.y * f0; a0.z += tv.z * f0; a0.w += tv.w * f0;
            a1.x += tv.x * f1; a1.y += tv.y * f1; a1.z += tv.z * f1; a1.w += tv.w * f1;
        }
    }
    *(float4*)&g_R[(l0 + lg * 2) * DD + d4 * 4]     = a0;
    *(float4*)&g_R[(l0 + lg * 2 + 1) * DD + d4 * 4] = a1;
}

// ---------------- kernel 3: split-bf16 mma.sync GEMM + fused epilogue ----------------
// CTA(lg, dh): l0 = lg*4 (4 l's), d0 = dh*64 (64 d's). 8 warps, warp w owns c-tile [16w,16w+16).
// H_l[c,d] = sum_m (mask_l[m]*a[m,c]) * tx[m,d]   (K = m, swept in rounds of 32)
// out1[l,d] = sum_c a[l,c]*Wlo[d,c]*H_l[c,d] + blo[d]*R[l,d]
// SMEM offsets (bytes): MKP=0(256) SA4=256(2048) U=2304
//   main: AH=U+0(8704) AM=U+8704(8704) BH=U+17408(4608) BM=U+22016(4608)
//   epi : WLO=U+0(33792) EP=U+33792(8192)   -> total 44288
__global__ __launch_bounds__(256, 1) void cop_kernel(
    const int*   __restrict__ mask, const float* __restrict__ Wlo,
    const float* __restrict__ blo)
{
    extern __shared__ char sm[];
    unsigned* s_mkp = (unsigned*)(sm);            // [4][16]
    float*    s_a   = (float*)(sm + 256);         // [4][128]
    unsigned* sAh   = (unsigned*)(sm + 2304);           // [16][136]
    unsigned* sAm   = (unsigned*)(sm + 2304 + 8704);    // [16][136]
    unsigned* sBh   = (unsigned*)(sm + 2304 + 17408);   // [16][72]
    unsigned* sBm   = (unsigned*)(sm + 2304 + 22016);   // [16][72]
    float*    s_wlo = (float*)(sm + 2304);              // [64][132] (epilogue)
    float*    s_ep  = (float*)(sm + 2304 + 33792);      // [8][4][64]

    const int t    = threadIdx.x;
    const int w    = t >> 5;
    const int lane = t & 31;
    const int gid  = lane >> 2;
    const int tig  = lane & 3;
    const int ct0  = w * 16;
    const int l0   = blockIdx.x * LP;
    const int d0   = blockIdx.y * 64;

    // stage a_l rows for epilogue weights (persistent region)
    #pragma unroll
    for (int i = 0; i < 2; i++) {
        int idx = t + 256 * i;
        s_a[idx] = g_a[(l0 + (idx >> 7)) * DD + (idx & 127)];
    }

    float acc[LP][8][4];
    #pragma unroll
    for (int l = 0; l < LP; l++)
        #pragma unroll
        for (int dg = 0; dg < 8; dg++)
            #pragma unroll
            for (int q = 0; q < 4; q++) acc[l][dg][q] = 0.f;

    for (int r = 0; r < 32; r++) {
        const int m0 = r * 32;
        __syncthreads();
        // mask pair words: 0x0000/0xFFFF per bf16 half
        if (t < 64) {
            int l = t >> 4, p = t & 15;
            int ma = mask[(l0 + l) * LLEN + m0 + 2 * p];
            int mb = mask[(l0 + l) * LLEN + m0 + 2 * p + 1];
            s_mkp[l * 16 + p] = (ma ? 0x0000FFFFu : 0u) | (mb ? 0xFFFF0000u : 0u);
        }
        // A: 16 pairs x 128 c  (pair kp = m (2kp, 2kp+1))
        #pragma unroll
        for (int i = 0; i < 8; i++) {
            int idx = t + 256 * i;
            int kp = idx >> 7, c = idx & 127;
            float x0 = g_a[(m0 + 2 * kp) * DD + c];
            float x1 = g_a[(m0 + 2 * kp + 1) * DD + c];
            unsigned uh, um; split_bf16(x0, x1, uh, um);
            sAh[kp * 136 + c] = uh; sAm[kp * 136 + c] = um;
        }
        // B: 16 pairs x 64 d
        #pragma unroll
        for (int i = 0; i < 4; i++) {
            int idx = t + 256 * i;
            int kp = idx >> 6, dc = idx & 63;
            float x0 = g_tx[(m0 + 2 * kp) * DD + d0 + dc];
            float x1 = g_tx[(m0 + 2 * kp + 1) * DD + d0 + dc];
            unsigned uh, um; split_bf16(x0, x1, uh, um);
            sBh[kp * 72 + dc] = uh; sBm[kp * 72 + dc] = um;
        }
        __syncthreads();

        #pragma unroll
        for (int s = 0; s < 2; s++) {
            const int kb = 8 * s;
            // raw A fragments (hi & mid)
            unsigned ah0 = sAh[(kb + tig) * 136 + ct0 + gid];
            unsigned ah1 = sAh[(kb + tig) * 136 + ct0 + gid + 8];
            unsigned ah2 = sAh[(kb + tig + 4) * 136 + ct0 + gid];
            unsigned ah3 = sAh[(kb + tig + 4) * 136 + ct0 + gid + 8];
            unsigned am0 = sAm[(kb + tig) * 136 + ct0 + gid];
            unsigned am1 = sAm[(kb + tig) * 136 + ct0 + gid + 8];
            unsigned am2 = sAm[(kb + tig + 4) * 136 + ct0 + gid];
            unsigned am3 = sAm[(kb + tig + 4) * 136 + ct0 + gid + 8];
            unsigned mkl[LP], mkh[LP];
            #pragma unroll
            for (int l = 0; l < LP; l++) {
                mkl[l] = s_mkp[l * 16 + kb + tig];
                mkh[l] = s_mkp[l * 16 + kb + tig + 4];
            }
            unsigned b0[8], b1[8];
            #pragma unroll
            for (int dg = 0; dg < 8; dg++) {
                b0[dg] = sBh[(kb + tig) * 72 + dg * 8 + gid];
                b1[dg] = sBh[(kb + tig + 4) * 72 + dg * 8 + gid];
            }
            // hh
            #pragma unroll
            for (int l = 0; l < LP; l++) {
                unsigned x0 = ah0 & mkl[l], x1 = ah1 & mkl[l];
                unsigned x2 = ah2 & mkh[l], x3 = ah3 & mkh[l];
                #pragma unroll
                for (int dg = 0; dg < 8; dg++)
                    mma_bf16(acc[l][dg], x0, x1, x2, x3, b0[dg], b1[dg]);
            }
            // mh (A-mid x B-hi)
            #pragma unroll
            for (int l = 0; l < LP; l++) {
                unsigned x0 = am0 & mkl[l], x1 = am1 & mkl[l];
                unsigned x2 = am2 & mkh[l], x3 = am3 & mkh[l];
                #pragma unroll
                for (int dg = 0; dg < 8; dg++)
                    mma_bf16(acc[l][dg], x0, x1, x2, x3, b0[dg], b1[dg]);
            }
            // hm (A-hi x B-mid)
            #pragma unroll
            for (int dg = 0; dg < 8; dg++) {
                b0[dg] = sBm[(kb + tig) * 72 + dg * 8 + gid];
                b1[dg] = sBm[(kb + tig + 4) * 72 + dg * 8 + gid];
            }
            #pragma unroll
            for (int l = 0; l < LP; l++) {
                unsigned x0 = ah0 & mkl[l], x1 = ah1 & mkl[l];
                unsigned x2 = ah2 & mkh[l], x3 = ah3 & mkh[l];
                #pragma unroll
                for (int dg = 0; dg < 8; dg++)
                    mma_bf16(acc[l][dg], x0, x1, x2, x3, b0[dg], b1[dg]);
            }
        }
    }

    // ---- epilogue: contract H over c with a_l[c]*Wlo[d,c], reduce, add blo*R ----
    __syncthreads();
    #pragma unroll
    for (int i = 0; i < 32; i++) {
        int idx = t + 256 * i;
        int dd = idx >> 7, c = idx & 127;
        s_wlo[dd * 132 + c] = Wlo[(d0 + dd) * DD + c];
    }
    __syncthreads();

    const int cA = ct0 + gid, cB = cA + 8;
    #pragma unroll
    for (int l = 0; l < LP; l++) {
        const float aA = s_a[l * DD + cA];
        const float aB = s_a[l * DD + cB];
        float pd[16];
        #pragma unroll
        for (int dg = 0; dg < 8; dg++) {
            const int dl0 = dg * 8 + 2 * tig;
            float w0  = s_wlo[dl0 * 132 + cA],       w1  = s_wlo[(dl0 + 1) * 132 + cA];
            float w0b = s_wlo[dl0 * 132 + cB],       w1b = s_wlo[(dl0 + 1) * 132 + cB];
            pd[2 * dg]     = acc[l][dg][0] * (aA * w0)  + acc[l][dg][2] * (aB * w0b);
            pd[2 * dg + 1] = acc[l][dg][1] * (aA * w1)  + acc[l][dg][3] * (aB * w1b);
        }
        #pragma unroll
        for (int off = 16; off >= 4; off >>= 1)
            #pragma unroll
            for (int q = 0; q < 16; q++)
                pd[q] += __shfl_down_sync(0xffffffffu, pd[q], off);
        if (lane < 4) {
            #pragma unroll
            for (int dg = 0; dg < 8; dg++) {
                s_ep[w * 256 + l * 64 + dg * 8 + 2 * lane]     = pd[2 * dg];
                s_ep[w * 256 + l * 64 + dg * 8 + 2 * lane + 1] = pd[2 * dg + 1];
            }
        }
    }
    __syncthreads();
    {
        const int l = t >> 6, dloc = t & 63;
        const int gl = l0 + l, d = d0 + dloc;
        float v = s_ep[t] + s_ep[256 + t] + s_ep[512 + t] + s_ep[768 + t]
                + s_ep[1024 + t] + s_ep[1280 + t] + s_ep[1536 + t] + s_ep[1792 + t];
        v += blo[d] * g_R[gl * DD + d];
        g_o1[gl * DD + d] = v;
    }
}

// ---------------- kernel 4: residual + LayerNorm ----------------
__global__ __launch_bounds__(128) void ln_kernel(
    const float* __restrict__ x,
    const float* __restrict__ gamma, const float* __restrict__ beta,
    float* __restrict__ out)
{
    __shared__ float w1[4], w2[4];
    __shared__ float mu_s, rstd_s;
    const int l = blockIdx.x;
    const int d = threadIdx.x;

    float y = x[l * DD + d] + g_o1[l * DD + d];

    float s1 = y, s2 = y * y;
    #pragma unroll
    for (int off = 16; off > 0; off >>= 1) {
        s1 += __shfl_down_sync(0xffffffffu, s1, off);
        s2 += __shfl_down_sync(0xffffffffu, s2, off);
    }
    const int wid = d >> 5, lid = d & 31;
    if (lid == 0) { w1[wid] = s1; w2[wid] = s2; }
    __syncthreads();
    if (d == 0) {
        float t1 = w1[0] + w1[1] + w1[2] + w1[3];
        float t2 = w2[0] + w2[1] + w2[2] + w2[3];
        float mu = t1 * (1.f / DD);
        float var = t2 * (1.f / DD) - mu * mu;
        mu_s = mu; rstd_s = rsqrtf(var + EPSF);
    }
    __syncthreads();
    out[l * DD + d] = (y - mu_s) * rstd_s * gamma[d] + beta[d];
}

// ---------------- launch ----------------
extern "C" void kernel_launch(void* const* d_in, const int* in_sizes, int n_in,
                              void* d_out, int out_size)
{
    (void)in_sizes; (void)n_in; (void)out_size;
    const float* x     = (const float*)d_in[0];
    const int*   mask  = (const int*)  d_in[1];
    const float* Wl    = (const float*)d_in[2];
    const float* bl    = (const float*)d_in[3];
    const float* Wlo   = (const float*)d_in[4];
    const float* blo   = (const float*)d_in[5];
    const float* Wl2   = (const float*)d_in[6];
    const float* bl2   = (const float*)d_in[7];
    const float* gamma = (const float*)d_in[8];
    const float* beta  = (const float*)d_in[9];
    float* out = (float*)d_out;

    proj_kernel<<<128, 256>>>(x, Wl, bl, Wl2, bl2);
    r_kernel<<<64, 256>>>(mask);
    cop_kernel<<<dim3(LLEN / LP, 2), 256, 44288>>>(mask, Wlo, blo);
    ln_kernel<<<1024, 128>>>(x, gamma, beta, out);
}

// round 4
// speedup vs baseline: 2.3876x; 1.0233x over previous
#include <cuda_runtime.h>
#include <cuda_bf16.h>

#define LLEN 1024
#define DD   128
#define EPSF 1e-5f
#define LP   4

// ---------------- scratch (device globals; no allocation) ----------------
__device__ float    g_a  [LLEN * DD];
__device__ float    g_tx [LLEN * DD];
__device__ float    g_R  [LLEN * DD];
__device__ float    g_o1 [LLEN * DD];
__device__ unsigned g_ah [512 * DD];    // packed bf16 pairs of a   (hi)
__device__ unsigned g_am [512 * DD];    // packed bf16 pairs of a   (mid)
__device__ unsigned g_bh [512 * DD];    // packed bf16 pairs of tx  (hi)
__device__ unsigned g_bm [512 * DD];    // packed bf16 pairs of tx  (mid)
__device__ unsigned g_mkp[LLEN * 512];  // mask pair-words per l

// ---------------- helpers ----------------
__device__ __forceinline__ unsigned pack_bf16x2(float lo, float hi) {
    unsigned u;
    asm("cvt.rn.bf16x2.f32 %0, %1, %2;" : "=r"(u) : "f"(hi), "f"(lo));
    return u;
}
__device__ __forceinline__ void split_bf16(float x0, float x1, unsigned& uh, unsigned& um) {
    uh = pack_bf16x2(x0, x1);
    float h0 = __uint_as_float(uh << 16);
    float h1 = __uint_as_float(uh & 0xFFFF0000u);
    um = pack_bf16x2(x0 - h0, x1 - h1);
}
__device__ __forceinline__ void mma_bf16(float* c, unsigned a0, unsigned a1, unsigned a2,
                                         unsigned a3, unsigned b0, unsigned b1) {
    asm volatile(
        "mma.sync.aligned.m16n8k16.row.col.f32.bf16.bf16.f32 "
        "{%0,%1,%2,%3}, {%4,%5,%6,%7}, {%8,%9}, {%0,%1,%2,%3};"
        : "+f"(c[0]), "+f"(c[1]), "+f"(c[2]), "+f"(c[3])
        : "r"(a0), "r"(a1), "r"(a2), "r"(a3), "r"(b0), "r"(b1));
}

// ---------------- kernel 1: projections ----------------
__global__ __launch_bounds__(256) void proj_kernel(
    const float* __restrict__ x,
    const float* __restrict__ Wl,  const float* __restrict__ bl,
    const float* __restrict__ Wl2, const float* __restrict__ bl2)
{
    __shared__ float xs[8 * DD];
    __shared__ float ws[32 * 129];
    const int t = threadIdx.x, l0 = blockIdx.x * 8;
    const int dloc = t & 31, lrow = t >> 5;
    for (int i = t; i < 8 * DD; i += 256) xs[i] = x[l0 * DD + i];
    for (int mat = 0; mat < 2; mat++) {
        const float* W    = mat ? Wl2 : Wl;
        const float* bias = mat ? bl2 : bl;
        float*       outp = mat ? g_tx : g_a;
        for (int dc = 0; dc < 4; dc++) {
            const int d0 = dc * 32;
            __syncthreads();
            for (int i = t; i < 32 * DD; i += 256) {
                int r = i >> 7, c = i & 127;
                ws[r * 129 + c] = W[(d0 + r) * DD + c];
            }
            __syncthreads();
            float acc = 0.f;
            #pragma unroll 8
            for (int c = 0; c < DD; c++) acc += xs[lrow * DD + c] * ws[dloc * 129 + c];
            outp[(l0 + lrow) * DD + d0 + dloc] = acc + bias[d0 + dloc];
        }
    }
}

// ---------------- kernel 2a: split a/tx into packed bf16 pair-words ----------------
__global__ __launch_bounds__(256) void prep_split_kernel()
{
    const int b = blockIdx.x;                       // 0..511
    const int idx = (b & 255) * 256 + threadIdx.x;  // 0..65535
    const int kp = idx >> 7, c = idx & 127;
    const float* src = (b < 256) ? g_a : g_tx;
    unsigned* dh = (b < 256) ? g_ah : g_bh;
    unsigned* dm = (b < 256) ? g_am : g_bm;
    float x0 = src[(2 * kp) * DD + c];
    float x1 = src[(2 * kp + 1) * DD + c];
    unsigned uh, um; split_bf16(x0, x1, uh, um);
    dh[kp * DD + c] = uh; dm[kp * DD + c] = um;
}

// ---------------- kernel 2b: mask pair-words ----------------
__global__ __launch_bounds__(256) void prep_mask_kernel(const int* __restrict__ mask)
{
    const int idx = blockIdx.x * 256 + threadIdx.x;   // 0..524287
    const int l = idx >> 9, kp = idx & 511;
    int ma = mask[l * LLEN + 2 * kp];
    int mb = mask[l * LLEN + 2 * kp + 1];
    g_mkp[idx] = (ma ? 0x0000FFFFu : 0u) | (mb ? 0xFFFF0000u : 0u);
}

// ---------------- kernel 3: R[l,d] (half grid per launch) ----------------
__global__ __launch_bounds__(256) void r_kernel(const int* __restrict__ mask, int blk0)
{
    __shared__ float s_txc[64 * DD];
    __shared__ float s_mk [16 * 64];
    const int t = threadIdx.x;
    const int l0 = (blk0 + blockIdx.x) * 16;
    const int d4 = t & 31, lg = t >> 5;
    float4 a0 = {0.f,0.f,0.f,0.f}, a1 = {0.f,0.f,0.f,0.f};
    for (int ch = 0; ch < 16; ch++) {
        const int m0 = ch * 64;
        __syncthreads();
        #pragma unroll
        for (int r = 0; r < 8; r++) {
            int idx = t + 256 * r;
            int rw = idx >> 5, c4 = idx & 31;
            *(float4*)&s_txc[rw * DD + c4 * 4] = *(const float4*)&g_tx[(m0 + rw) * DD + c4 * 4];
        }
        #pragma unroll
        for (int r = 0; r < 4; r++) {
            int idx = t + 256 * r;
            int li = idx >> 6, mm = idx & 63;
            s_mk[li * 64 + mm] = (mask[(l0 + li) * LLEN + m0 + mm] != 0) ? 1.f : 0.f;
        }
        __syncthreads();
        #pragma unroll 4
        for (int mm = 0; mm < 64; mm++) {
            float4 tv = *(float4*)&s_txc[mm * DD + d4 * 4];
            float f0 = s_mk[(lg * 2) * 64 + mm];
            float f1 = s_mk[(lg * 2 + 1) * 64 + mm];
            a0.x += tv.x * f0; a0.y += tv.y * f0; a0.z += tv.z * f0; a0.w += tv.w * f0;
            a1.x += tv.x * f1; a1.y += tv.y * f1; a1.z += tv.z * f1; a1.w += tv.w * f1;
        }
    }
    *(float4*)&g_R[(l0 + lg * 2) * DD + d4 * 4]     = a0;
    *(float4*)&g_R[(l0 + lg * 2 + 1) * DD + d4 * 4] = a1;
}

// ---------------- kernel 4: mma.sync GEMM + fused epilogue ----------------
// SMEM map (bytes): a_l 0..2048, masks 2048..10240,
//   Ah @10240 (8704), Am @18944 (8704), Bh @27648 (4608), Bm @32256 (4608)
// Epilogue reuse: wlo @2048 (33792), ep @35840 (8192). Dynamic size 44032.
__global__ __launch_bounds__(256, 1) void cop_kernel(
    const float* __restrict__ Wlo, const float* __restrict__ blo)
{
    extern __shared__ char sm[];
    float*    s_a  = (float*)sm;                 // [4][128]
    unsigned* s_mk = (unsigned*)(sm + 2048);     // [4][512]
    unsigned* sAh  = (unsigned*)(sm + 10240);    // [16][136]
    unsigned* sAm  = (unsigned*)(sm + 18944);    // [16][136]
    unsigned* sBh  = (unsigned*)(sm + 27648);    // [16][72]
    unsigned* sBm  = (unsigned*)(sm + 32256);    // [16][72]
    float*    s_wlo = (float*)(sm + 2048);       // [64][132] epilogue
    float*    s_ep  = (float*)(sm + 35840);      // [8][4][64] epilogue

    const int t    = threadIdx.x;
    const int w    = t >> 5;
    const int lane = t & 31;
    const int gid  = lane >> 2;
    const int tig  = lane & 3;
    const int ct0  = w * 16;
    const int l0   = blockIdx.x * LP;
    const int d0   = blockIdx.y * 64;

    // one-time staging: a_l rows + all mask pair-words for these 4 l's
    #pragma unroll
    for (int i = 0; i < 2; i++) {
        int idx = t + 256 * i;
        s_a[idx] = g_a[(l0 + (idx >> 7)) * DD + (idx & 127)];
    }
    #pragma unroll
    for (int i = 0; i < 8; i++) {
        int idx = t + 256 * i;
        s_mk[idx] = g_mkp[(l0 + (idx >> 9)) * 512 + (idx & 511)];
    }

    float acc[LP][8][4];
    #pragma unroll
    for (int l = 0; l < LP; l++)
        #pragma unroll
        for (int dg = 0; dg < 8; dg++)
            #pragma unroll
            for (int q = 0; q < 4; q++) acc[l][dg][q] = 0.f;

    // prefetch indices
    const int kpA0 = t >> 5, c4A = t & 31;     // A: rows kpA0, kpA0+8; 4 u32 each
    const int kpB  = t >> 4, c4B = t & 15;     // B: row kpB; 4 u32
    const unsigned aIdx0 = kpA0 * 32 + c4A;    // uint4 index within 16x128 tile row block
    const unsigned bIdx  = kpB * 32 + (d0 >> 2) + c4B;

    uint4 pAh0, pAh1, pAm0, pAm1, pBh, pBm;
    {
        const uint4* Ah4 = (const uint4*)g_ah; const uint4* Am4 = (const uint4*)g_am;
        const uint4* Bh4 = (const uint4*)g_bh; const uint4* Bm4 = (const uint4*)g_bm;
        pAh0 = Ah4[aIdx0]; pAh1 = Ah4[aIdx0 + 256];
        pAm0 = Am4[aIdx0]; pAm1 = Am4[aIdx0 + 256];
        pBh  = Bh4[bIdx];  pBm  = Bm4[bIdx];
    }

    #pragma unroll 1
    for (int r = 0; r < 32; r++) {
        __syncthreads();   // previous round's MMA reads done (r=0: covers init staging)
        // STS staged regs (same layout as verified R3 tiles)
        *(uint4*)&sAh[kpA0 * 136 + c4A * 4]       = pAh0;
        *(uint4*)&sAh[(kpA0 + 8) * 136 + c4A * 4] = pAh1;
        *(uint4*)&sAm[kpA0 * 136 + c4A * 4]       = pAm0;
        *(uint4*)&sAm[(kpA0 + 8) * 136 + c4A * 4] = pAm1;
        *(uint4*)&sBh[kpB * 72 + c4B * 4]         = pBh;
        *(uint4*)&sBm[kpB * 72 + c4B * 4]         = pBm;
        __syncthreads();
        if (r < 31) {
            const unsigned ofs = (unsigned)(r + 1) * 16 * 32;   // 16 rows * 32 uint4
            const uint4* Ah4 = (const uint4*)g_ah; const uint4* Am4 = (const uint4*)g_am;
            const uint4* Bh4 = (const uint4*)g_bh; const uint4* Bm4 = (const uint4*)g_bm;
            pAh0 = Ah4[ofs + aIdx0]; pAh1 = Ah4[ofs + aIdx0 + 256];
            pAm0 = Am4[ofs + aIdx0]; pAm1 = Am4[ofs + aIdx0 + 256];
            pBh  = Bh4[ofs + bIdx];  pBm  = Bm4[ofs + bIdx];
        }
        const int kpg = r * 16;
        #pragma unroll
        for (int s = 0; s < 2; s++) {
            const int kb = 8 * s;
            unsigned ah0 = sAh[(kb + tig) * 136 + ct0 + gid];
            unsigned ah1 = sAh[(kb + tig) * 136 + ct0 + gid + 8];
            unsigned ah2 = sAh[(kb + tig + 4) * 136 + ct0 + gid];
            unsigned ah3 = sAh[(kb + tig + 4) * 136 + ct0 + gid + 8];
            unsigned am0 = sAm[(kb + tig) * 136 + ct0 + gid];
            unsigned am1 = sAm[(kb + tig) * 136 + ct0 + gid + 8];
            unsigned am2 = sAm[(kb + tig + 4) * 136 + ct0 + gid];
            unsigned am3 = sAm[(kb + tig + 4) * 136 + ct0 + gid + 8];
            unsigned mkl[LP], mkh[LP];
            #pragma unroll
            for (int l = 0; l < LP; l++) {
                mkl[l] = s_mk[l * 512 + kpg + kb + tig];
                mkh[l] = s_mk[l * 512 + kpg + kb + tig + 4];
            }
            unsigned b0[8], b1[8];
            #pragma unroll
            for (int dg = 0; dg < 8; dg++) {
                b0[dg] = sBh[(kb + tig) * 72 + dg * 8 + gid];
                b1[dg] = sBh[(kb + tig + 4) * 72 + dg * 8 + gid];
            }
            #pragma unroll
            for (int l = 0; l < LP; l++) {      // hh
                unsigned x0 = ah0 & mkl[l], x1 = ah1 & mkl[l];
                unsigned x2 = ah2 & mkh[l], x3 = ah3 & mkh[l];
                #pragma unroll
                for (int dg = 0; dg < 8; dg++)
                    mma_bf16(acc[l][dg], x0, x1, x2, x3, b0[dg], b1[dg]);
            }
            #pragma unroll
            for (int l = 0; l < LP; l++) {      // mh
                unsigned x0 = am0 & mkl[l], x1 = am1 & mkl[l];
                unsigned x2 = am2 & mkh[l], x3 = am3 & mkh[l];
                #pragma unroll
                for (int dg = 0; dg < 8; dg++)
                    mma_bf16(acc[l][dg], x0, x1, x2, x3, b0[dg], b1[dg]);
            }
            #pragma unroll
            for (int dg = 0; dg < 8; dg++) {
                b0[dg] = sBm[(kb + tig) * 72 + dg * 8 + gid];
                b1[dg] = sBm[(kb + tig + 4) * 72 + dg * 8 + gid];
            }
            #pragma unroll
            for (int l = 0; l < LP; l++) {      // hm
                unsigned x0 = ah0 & mkl[l], x1 = ah1 & mkl[l];
                unsigned x2 = ah2 & mkh[l], x3 = ah3 & mkh[l];
                #pragma unroll
                for (int dg = 0; dg < 8; dg++)
                    mma_bf16(acc[l][dg], x0, x1, x2, x3, b0[dg], b1[dg]);
            }
        }
    }

    // ---- epilogue (verified in R3): sum_c a_l[c]*Wlo[d,c]*H, reduce, + blo*R ----
    __syncthreads();
    #pragma unroll
    for (int i = 0; i < 32; i++) {
        int idx = t + 256 * i;
        int dd = idx >> 7, c = idx & 127;
        s_wlo[dd * 132 + c] = Wlo[(d0 + dd) * DD + c];
    }
    __syncthreads();

    const int cA = ct0 + gid, cB = cA + 8;
    #pragma unroll
    for (int l = 0; l < LP; l++) {
        const float aA = s_a[l * DD + cA];
        const float aB = s_a[l * DD + cB];
        float pd[16];
        #pragma unroll
        for (int dg = 0; dg < 8; dg++) {
            const int dl0 = dg * 8 + 2 * tig;
            float w0  = s_wlo[dl0 * 132 + cA],  w1  = s_wlo[(dl0 + 1) * 132 + cA];
            float w0b = s_wlo[dl0 * 132 + cB],  w1b = s_wlo[(dl0 + 1) * 132 + cB];
            pd[2 * dg]     = acc[l][dg][0] * (aA * w0) + acc[l][dg][2] * (aB * w0b);
            pd[2 * dg + 1] = acc[l][dg][1] * (aA * w1) + acc[l][dg][3] * (aB * w1b);
        }
        #pragma unroll
        for (int off = 16; off >= 4; off >>= 1)
            #pragma unroll
            for (int q = 0; q < 16; q++)
                pd[q] += __shfl_down_sync(0xffffffffu, pd[q], off);
        if (lane < 4) {
            #pragma unroll
            for (int dg = 0; dg < 8; dg++) {
                s_ep[w * 256 + l * 64 + dg * 8 + 2 * lane]     = pd[2 * dg];
                s_ep[w * 256 + l * 64 + dg * 8 + 2 * lane + 1] = pd[2 * dg + 1];
            }
        }
    }
    __syncthreads();
    {
        const int l = t >> 6, dloc = t & 63;
        const int gl = l0 + l, d = d0 + dloc;
        float v = s_ep[t] + s_ep[256 + t] + s_ep[512 + t] + s_ep[768 + t]
                + s_ep[1024 + t] + s_ep[1280 + t] + s_ep[1536 + t] + s_ep[1792 + t];
        v += blo[d] * g_R[gl * DD + d];
        g_o1[gl * DD + d] = v;
    }
}

// ---------------- kernel 5: residual + LayerNorm ----------------
__global__ __launch_bounds__(128) void ln_kernel(
    const float* __restrict__ x,
    const float* __restrict__ gamma, const float* __restrict__ beta,
    float* __restrict__ out)
{
    __shared__ float w1[4], w2[4];
    __shared__ float mu_s, rstd_s;
    const int l = blockIdx.x;
    const int d = threadIdx.x;
    float y = x[l * DD + d] + g_o1[l * DD + d];
    float s1 = y, s2 = y * y;
    #pragma unroll
    for (int off = 16; off > 0; off >>= 1) {
        s1 += __shfl_down_sync(0xffffffffu, s1, off);
        s2 += __shfl_down_sync(0xffffffffu, s2, off);
    }
    const int wid = d >> 5, lid = d & 31;
    if (lid == 0) { w1[wid] = s1; w2[wid] = s2; }
    __syncthreads();
    if (d == 0) {
        float t1 = w1[0] + w1[1] + w1[2] + w1[3];
        float t2 = w2[0] + w2[1] + w2[2] + w2[3];
        float mu = t1 * (1.f / DD);
        float var = t2 * (1.f / DD) - mu * mu;
        mu_s = mu; rstd_s = rsqrtf(var + EPSF);
    }
    __syncthreads();
    out[l * DD + d] = (y - mu_s) * rstd_s * gamma[d] + beta[d];
}

// ---------------- launch (cop is 6th launch for ncu -s 5 capture) ----------------
extern "C" void kernel_launch(void* const* d_in, const int* in_sizes, int n_in,
                              void* d_out, int out_size)
{
    (void)in_sizes; (void)n_in; (void)out_size;
    const float* x     = (const float*)d_in[0];
    const int*   mask  = (const int*)  d_in[1];
    const float* Wl    = (const float*)d_in[2];
    const float* bl    = (const float*)d_in[3];
    const float* Wlo   = (const float*)d_in[4];
    const float* blo   = (const float*)d_in[5];
    const float* Wl2   = (const float*)d_in[6];
    const float* bl2   = (const float*)d_in[7];
    const float* gamma = (const float*)d_in[8];
    const float* beta  = (const float*)d_in[9];
    float* out = (float*)d_out;

    proj_kernel<<<128, 256>>>(x, Wl, bl, Wl2, bl2);          // 1
    prep_split_kernel<<<512, 256>>>();                       // 2
    prep_mask_kernel<<<2048, 256>>>(mask);                   // 3
    r_kernel<<<32, 256>>>(mask, 0);                          // 4
    r_kernel<<<32, 256>>>(mask, 32);                         // 5
    cop_kernel<<<dim3(LLEN / LP, 2), 256, 44032>>>(Wlo, blo);// 6
    ln_kernel<<<1024, 128>>>(x, gamma, beta, out);           // 7
}

// round 5
// speedup vs baseline: 2.4188x; 1.0131x over previous
#include <cuda_runtime.h>
#include <cuda_bf16.h>

#define LLEN 1024
#define DD   128
#define EPSF 1e-5f
#define LP   4

// ---------------- scratch (device globals; no allocation) ----------------
__device__ float    g_a  [LLEN * DD];
__device__ float    g_tx [LLEN * DD];
__device__ float    g_Rp [4 * LLEN * DD];   // R partials over 4 m-groups
__device__ float    g_o1 [LLEN * DD];
__device__ unsigned g_ah [512 * DD];
__device__ unsigned g_am [512 * DD];
__device__ unsigned g_bh [512 * DD];
__device__ unsigned g_bm [512 * DD];
__device__ unsigned g_mkp[LLEN * 512];

// ---------------- helpers ----------------
__device__ __forceinline__ unsigned pack_bf16x2(float lo, float hi) {
    unsigned u;
    asm("cvt.rn.bf16x2.f32 %0, %1, %2;" : "=r"(u) : "f"(hi), "f"(lo));
    return u;
}
__device__ __forceinline__ void split_bf16(float x0, float x1, unsigned& uh, unsigned& um) {
    uh = pack_bf16x2(x0, x1);
    float h0 = __uint_as_float(uh << 16);
    float h1 = __uint_as_float(uh & 0xFFFF0000u);
    um = pack_bf16x2(x0 - h0, x1 - h1);
}
__device__ __forceinline__ void mma_bf16(float* c, unsigned a0, unsigned a1, unsigned a2,
                                         unsigned a3, unsigned b0, unsigned b1) {
    asm volatile(
        "mma.sync.aligned.m16n8k16.row.col.f32.bf16.bf16.f32 "
        "{%0,%1,%2,%3}, {%4,%5,%6,%7}, {%8,%9}, {%0,%1,%2,%3};"
        : "+f"(c[0]), "+f"(c[1]), "+f"(c[2]), "+f"(c[3])
        : "r"(a0), "r"(a1), "r"(a2), "r"(a3), "r"(b0), "r"(b1));
}

// ---------------- kernel 1: projections ----------------
__global__ __launch_bounds__(256) void proj_kernel(
    const float* __restrict__ x,
    const float* __restrict__ Wl,  const float* __restrict__ bl,
    const float* __restrict__ Wl2, const float* __restrict__ bl2)
{
    __shared__ float xs[8 * DD];
    __shared__ float ws[32 * 129];
    const int t = threadIdx.x, l0 = blockIdx.x * 8;
    const int dloc = t & 31, lrow = t >> 5;
    for (int i = t; i < 8 * DD; i += 256) xs[i] = x[l0 * DD + i];
    for (int mat = 0; mat < 2; mat++) {
        const float* W    = mat ? Wl2 : Wl;
        const float* bias = mat ? bl2 : bl;
        float*       outp = mat ? g_tx : g_a;
        for (int dc = 0; dc < 4; dc++) {
            const int d0 = dc * 32;
            __syncthreads();
            for (int i = t; i < 32 * DD; i += 256) {
                int r = i >> 7, c = i & 127;
                ws[r * 129 + c] = W[(d0 + r) * DD + c];
            }
            __syncthreads();
            float acc = 0.f;
            #pragma unroll 8
            for (int c = 0; c < DD; c++) acc += xs[lrow * DD + c] * ws[dloc * 129 + c];
            outp[(l0 + lrow) * DD + d0 + dloc] = acc + bias[d0 + dloc];
        }
    }
}

// ---------------- kernel 2a: split a/tx into packed bf16 pair-words ----------------
__global__ __launch_bounds__(256) void prep_split_kernel()
{
    const int b = blockIdx.x;
    const int idx = (b & 255) * 256 + threadIdx.x;
    const int kp = idx >> 7, c = idx & 127;
    const float* src = (b < 256) ? g_a : g_tx;
    unsigned* dh = (b < 256) ? g_ah : g_bh;
    unsigned* dm = (b < 256) ? g_am : g_bm;
    float x0 = src[(2 * kp) * DD + c];
    float x1 = src[(2 * kp + 1) * DD + c];
    unsigned uh, um; split_bf16(x0, x1, uh, um);
    dh[kp * DD + c] = uh; dm[kp * DD + c] = um;
}

// ---------------- kernel 2b: mask pair-words ----------------
__global__ __launch_bounds__(256) void prep_mask_kernel(const int* __restrict__ mask)
{
    const int idx = blockIdx.x * 256 + threadIdx.x;
    const int l = idx >> 9, kp = idx & 511;
    int ma = mask[l * LLEN + 2 * kp];
    int mb = mask[l * LLEN + 2 * kp + 1];
    g_mkp[idx] = (ma ? 0x0000FFFFu : 0u) | (mb ? 0xFFFF0000u : 0u);
}

// ---------------- kernel 3: R partials, grid (64 l-tiles, 4 m-groups) ----------------
__global__ __launch_bounds__(256) void r_kernel(const int* __restrict__ mask)
{
    __shared__ float s_txc[64 * DD];
    __shared__ float s_mk [16 * 64];
    const int t = threadIdx.x;
    const int l0 = blockIdx.x * 16;
    const int mg = blockIdx.y;
    const int d4 = t & 31, lg = t >> 5;
    float4 a0 = {0.f,0.f,0.f,0.f}, a1 = {0.f,0.f,0.f,0.f};
    for (int ch = 0; ch < 4; ch++) {
        const int m0 = mg * 256 + ch * 64;
        __syncthreads();
        #pragma unroll
        for (int r = 0; r < 8; r++) {
            int idx = t + 256 * r;
            int rw = idx >> 5, c4 = idx & 31;
            *(float4*)&s_txc[rw * DD + c4 * 4] = *(const float4*)&g_tx[(m0 + rw) * DD + c4 * 4];
        }
        #pragma unroll
        for (int r = 0; r < 4; r++) {
            int idx = t + 256 * r;
            int li = idx >> 6, mm = idx & 63;
            s_mk[li * 64 + mm] = (mask[(l0 + li) * LLEN + m0 + mm] != 0) ? 1.f : 0.f;
        }
        __syncthreads();
        #pragma unroll 4
        for (int mm = 0; mm < 64; mm++) {
            float4 tv = *(float4*)&s_txc[mm * DD + d4 * 4];
            float f0 = s_mk[(lg * 2) * 64 + mm];
            float f1 = s_mk[(lg * 2 + 1) * 64 + mm];
            a0.x += tv.x * f0; a0.y += tv.y * f0; a0.z += tv.z * f0; a0.w += tv.w * f0;
            a1.x += tv.x * f1; a1.y += tv.y * f1; a1.z += tv.z * f1; a1.w += tv.w * f1;
        }
    }
    *(float4*)&g_Rp[(mg * LLEN + l0 + lg * 2) * DD + d4 * 4]     = a0;
    *(float4*)&g_Rp[(mg * LLEN + l0 + lg * 2 + 1) * DD + d4 * 4] = a1;
}

// ---------------- kernel 4: mma.sync GEMM + fused epilogue (512 threads) ----------------
// 16 warps: warp w -> c-tile (w>>1)*16, d-offset (w&1)*32 within CTA's 64-d slab.
// SMEM: s_a 0..2048, s_mk 2048..10240, Ah@10240(8704) Am@18944(8704)
//       Bh@27648(4608) Bm@32256(4608); epilogue: wlo@2048, ep@35840(8192). Total 44032.
__global__ __launch_bounds__(512, 1) void cop_kernel(const float* __restrict__ Wlo)
{
    extern __shared__ char sm[];
    float*    s_a  = (float*)sm;
    unsigned* s_mk = (unsigned*)(sm + 2048);
    unsigned* sAh  = (unsigned*)(sm + 10240);
    unsigned* sAm  = (unsigned*)(sm + 18944);
    unsigned* sBh  = (unsigned*)(sm + 27648);
    unsigned* sBm  = (unsigned*)(sm + 32256);
    float*    s_wlo = (float*)(sm + 2048);
    float*    s_ep  = (float*)(sm + 35840);   // [16][4][32]

    const int t    = threadIdx.x;
    const int w    = t >> 5;
    const int lane = t & 31;
    const int gid  = lane >> 2;
    const int tig  = lane & 3;
    const int ct0  = (w >> 1) * 16;
    const int dofs = (w & 1) * 32;
    const int l0   = blockIdx.x * LP;
    const int d0   = blockIdx.y * 64;

    s_a[t] = g_a[(l0 + (t >> 7)) * DD + (t & 127)];
    #pragma unroll
    for (int i = 0; i < 4; i++) {
        int idx = t + 512 * i;
        s_mk[idx] = g_mkp[(l0 + (idx >> 9)) * 512 + (idx & 511)];
    }

    float acc[LP][4][4];
    #pragma unroll
    for (int l = 0; l < LP; l++)
        #pragma unroll
        for (int dg = 0; dg < 4; dg++)
            #pragma unroll
            for (int q = 0; q < 4; q++) acc[l][dg][q] = 0.f;

    // prefetch: A uint4 index == t (16 rows x 32 uint4); B for t<256
    const int kpB = t >> 4, c4B = t & 15;
    const unsigned bIdx = kpB * 32 + (d0 >> 2) + c4B;
    uint4 pAh, pAm, pBh, pBm;
    {
        const uint4* Ah4 = (const uint4*)g_ah; const uint4* Am4 = (const uint4*)g_am;
        pAh = Ah4[t]; pAm = Am4[t];
        if (t < 256) {
            const uint4* Bh4 = (const uint4*)g_bh; const uint4* Bm4 = (const uint4*)g_bm;
            pBh = Bh4[bIdx]; pBm = Bm4[bIdx];
        }
    }

    #pragma unroll 1
    for (int r = 0; r < 32; r++) {
        __syncthreads();
        *(uint4*)&sAh[(t >> 5) * 136 + (t & 31) * 4] = pAh;
        *(uint4*)&sAm[(t >> 5) * 136 + (t & 31) * 4] = pAm;
        if (t < 256) {
            *(uint4*)&sBh[kpB * 72 + c4B * 4] = pBh;
            *(uint4*)&sBm[kpB * 72 + c4B * 4] = pBm;
        }
        __syncthreads();
        if (r < 31) {
            const unsigned ofs = (unsigned)(r + 1) * 512;
            const uint4* Ah4 = (const uint4*)g_ah; const uint4* Am4 = (const uint4*)g_am;
            pAh = Ah4[ofs + t]; pAm = Am4[ofs + t];
            if (t < 256) {
                const uint4* Bh4 = (const uint4*)g_bh; const uint4* Bm4 = (const uint4*)g_bm;
                pBh = Bh4[ofs + bIdx]; pBm = Bm4[ofs + bIdx];
            }
        }
        const int kpg = r * 16;
        #pragma unroll
        for (int s = 0; s < 2; s++) {
            const int kb = 8 * s;
            unsigned ah0 = sAh[(kb + tig) * 136 + ct0 + gid];
            unsigned ah1 = sAh[(kb + tig) * 136 + ct0 + gid + 8];
            unsigned ah2 = sAh[(kb + tig + 4) * 136 + ct0 + gid];
            unsigned ah3 = sAh[(kb + tig + 4) * 136 + ct0 + gid + 8];
            unsigned am0 = sAm[(kb + tig) * 136 + ct0 + gid];
            unsigned am1 = sAm[(kb + tig) * 136 + ct0 + gid + 8];
            unsigned am2 = sAm[(kb + tig + 4) * 136 + ct0 + gid];
            unsigned am3 = sAm[(kb + tig + 4) * 136 + ct0 + gid + 8];
            unsigned mkl[LP], mkh[LP];
            #pragma unroll
            for (int l = 0; l < LP; l++) {
                mkl[l] = s_mk[l * 512 + kpg + kb + tig];
                mkh[l] = s_mk[l * 512 + kpg + kb + tig + 4];
            }
            unsigned b0[4], b1[4];
            #pragma unroll
            for (int dg = 0; dg < 4; dg++) {
                b0[dg] = sBh[(kb + tig) * 72 + dofs + dg * 8 + gid];
                b1[dg] = sBh[(kb + tig + 4) * 72 + dofs + dg * 8 + gid];
            }
            #pragma unroll
            for (int l = 0; l < LP; l++) {      // hh
                unsigned x0 = ah0 & mkl[l], x1 = ah1 & mkl[l];
                unsigned x2 = ah2 & mkh[l], x3 = ah3 & mkh[l];
                #pragma unroll
                for (int dg = 0; dg < 4; dg++)
                    mma_bf16(acc[l][dg], x0, x1, x2, x3, b0[dg], b1[dg]);
            }
            #pragma unroll
            for (int l = 0; l < LP; l++) {      // mh
                unsigned x0 = am0 & mkl[l], x1 = am1 & mkl[l];
                unsigned x2 = am2 & mkh[l], x3 = am3 & mkh[l];
                #pragma unroll
                for (int dg = 0; dg < 4; dg++)
                    mma_bf16(acc[l][dg], x0, x1, x2, x3, b0[dg], b1[dg]);
            }
            #pragma unroll
            for (int dg = 0; dg < 4; dg++) {
                b0[dg] = sBm[(kb + tig) * 72 + dofs + dg * 8 + gid];
                b1[dg] = sBm[(kb + tig + 4) * 72 + dofs + dg * 8 + gid];
            }
            #pragma unroll
            for (int l = 0; l < LP; l++) {      // hm
                unsigned x0 = ah0 & mkl[l], x1 = ah1 & mkl[l];
                unsigned x2 = ah2 & mkh[l], x3 = ah3 & mkh[l];
                #pragma unroll
                for (int dg = 0; dg < 4; dg++)
                    mma_bf16(acc[l][dg], x0, x1, x2, x3, b0[dg], b1[dg]);
            }
        }
    }

    // ---- epilogue: sum_c a_l[c]*Wlo[d,c]*H ----
    __syncthreads();
    #pragma unroll
    for (int i = 0; i < 16; i++) {
        int idx = t + 512 * i;
        int dd = idx >> 7, c = idx & 127;
        s_wlo[dd * 132 + c] = Wlo[(d0 + dd) * DD + c];
    }
    __syncthreads();

    const int cA = ct0 + gid, cB = cA + 8;
    #pragma unroll
    for (int l = 0; l < LP; l++) {
        const float aA = s_a[l * DD + cA];
        const float aB = s_a[l * DD + cB];
        float pd[8];
        #pragma unroll
        for (int dg = 0; dg < 4; dg++) {
            const int dl0 = dofs + dg * 8 + 2 * tig;
            float w0  = s_wlo[dl0 * 132 + cA],  w1  = s_wlo[(dl0 + 1) * 132 + cA];
            float w0b = s_wlo[dl0 * 132 + cB],  w1b = s_wlo[(dl0 + 1) * 132 + cB];
            pd[2 * dg]     = acc[l][dg][0] * (aA * w0) + acc[l][dg][2] * (aB * w0b);
            pd[2 * dg + 1] = acc[l][dg][1] * (aA * w1) + acc[l][dg][3] * (aB * w1b);
        }
        #pragma unroll
        for (int off = 16; off >= 4; off >>= 1)
            #pragma unroll
            for (int q = 0; q < 8; q++)
                pd[q] += __shfl_down_sync(0xffffffffu, pd[q], off);
        if (lane < 4) {
            #pragma unroll
            for (int dg = 0; dg < 4; dg++) {
                s_ep[w * 128 + l * 32 + dg * 8 + 2 * lane]     = pd[2 * dg];
                s_ep[w * 128 + l * 32 + dg * 8 + 2 * lane + 1] = pd[2 * dg + 1];
            }
        }
    }
    __syncthreads();
    if (t < 256) {
        const int l = t >> 6, dloc = t & 63;
        const int half = dloc >> 5, dl = dloc & 31;
        float v = 0.f;
        #pragma unroll
        for (int ct = 0; ct < 8; ct++)
            v += s_ep[(2 * ct + half) * 128 + l * 32 + dl];
        g_o1[(l0 + l) * DD + d0 + dloc] = v;
    }
}

// ---------------- kernel 5: residual + blo*R + LayerNorm ----------------
__global__ __launch_bounds__(128) void ln_kernel(
    const float* __restrict__ x,   const float* __restrict__ blo,
    const float* __restrict__ gamma, const float* __restrict__ beta,
    float* __restrict__ out)
{
    __shared__ float w1[4], w2[4];
    __shared__ float mu_s, rstd_s;
    const int l = blockIdx.x;
    const int d = threadIdx.x;
    float Rv = g_Rp[l * DD + d] + g_Rp[(LLEN + l) * DD + d]
             + g_Rp[(2 * LLEN + l) * DD + d] + g_Rp[(3 * LLEN + l) * DD + d];
    float y = x[l * DD + d] + g_o1[l * DD + d] + blo[d] * Rv;
    float s1 = y, s2 = y * y;
    #pragma unroll
    for (int off = 16; off > 0; off >>= 1) {
        s1 += __shfl_down_sync(0xffffffffu, s1, off);
        s2 += __shfl_down_sync(0xffffffffu, s2, off);
    }
    const int wid = d >> 5, lid = d & 31;
    if (lid == 0) { w1[wid] = s1; w2[wid] = s2; }
    __syncthreads();
    if (d == 0) {
        float t1 = w1[0] + w1[1] + w1[2] + w1[3];
        float t2 = w2[0] + w2[1] + w2[2] + w2[3];
        float mu = t1 * (1.f / DD);
        float var = t2 * (1.f / DD) - mu * mu;
        mu_s = mu; rstd_s = rsqrtf(var + EPSF);
    }
    __syncthreads();
    out[l * DD + d] = (y - mu_s) * rstd_s * gamma[d] + beta[d];
}

// ---------------- launch (cop 5th for ncu capture) ----------------
extern "C" void kernel_launch(void* const* d_in, const int* in_sizes, int n_in,
                              void* d_out, int out_size)
{
    (void)in_sizes; (void)n_in; (void)out_size;
    const float* x     = (const float*)d_in[0];
    const int*   mask  = (const int*)  d_in[1];
    const float* Wl    = (const float*)d_in[2];
    const float* bl    = (const float*)d_in[3];
    const float* Wlo   = (const float*)d_in[4];
    const float* blo   = (const float*)d_in[5];
    const float* Wl2   = (const float*)d_in[6];
    const float* bl2   = (const float*)d_in[7];
    const float* gamma = (const float*)d_in[8];
    const float* beta  = (const float*)d_in[9];
    float* out = (float*)d_out;

    proj_kernel<<<128, 256>>>(x, Wl, bl, Wl2, bl2);            // 1
    prep_split_kernel<<<512, 256>>>();                         // 2
    prep_mask_kernel<<<2048, 256>>>(mask);                     // 3
    r_kernel<<<dim3(64, 4), 256>>>(mask);                      // 4
    cop_kernel<<<dim3(LLEN / LP, 2), 512, 44032>>>(Wlo);       // 5
    ln_kernel<<<1024, 128>>>(x, blo, gamma, beta, out);        // 6
}

// round 6
// speedup vs baseline: 2.6988x; 1.1158x over previous
#include <cuda_runtime.h>
#include <cuda_bf16.h>

#define LLEN 1024
#define DD   128
#define EPSF 1e-5f
#define LP   4
#define NTILE 512   // 256 l-tiles x 2 d-halves

// ---------------- scratch (device globals; no allocation) ----------------
__device__ float    g_a  [LLEN * DD];
__device__ float    g_tx [LLEN * DD];
__device__ float    g_Rp [4 * LLEN * DD];
__device__ float    g_o1 [LLEN * DD];
__device__ unsigned g_ah [512 * DD];
__device__ unsigned g_am [512 * DD];
__device__ unsigned g_bh [512 * DD];
__device__ unsigned g_bm [512 * DD];
__device__ unsigned g_mkp[LLEN * 512];
__device__ unsigned g_tile_ctr;

// ---------------- helpers ----------------
__device__ __forceinline__ unsigned pack_bf16x2(float lo, float hi) {
    unsigned u;
    asm("cvt.rn.bf16x2.f32 %0, %1, %2;" : "=r"(u) : "f"(hi), "f"(lo));
    return u;
}
__device__ __forceinline__ void split_bf16(float x0, float x1, unsigned& uh, unsigned& um) {
    uh = pack_bf16x2(x0, x1);
    float h0 = __uint_as_float(uh << 16);
    float h1 = __uint_as_float(uh & 0xFFFF0000u);
    um = pack_bf16x2(x0 - h0, x1 - h1);
}
__device__ __forceinline__ void mma_bf16(float* c, unsigned a0, unsigned a1, unsigned a2,
                                         unsigned a3, unsigned b0, unsigned b1) {
    asm volatile(
        "mma.sync.aligned.m16n8k16.row.col.f32.bf16.bf16.f32 "
        "{%0,%1,%2,%3}, {%4,%5,%6,%7}, {%8,%9}, {%0,%1,%2,%3};"
        : "+f"(c[0]), "+f"(c[1]), "+f"(c[2]), "+f"(c[3])
        : "r"(a0), "r"(a1), "r"(a2), "r"(a3), "r"(b0), "r"(b1));
}

// ---------------- kernel 1: projections + fused bf16 split ----------------
__global__ __launch_bounds__(256) void proj_kernel(
    const float* __restrict__ x,
    const float* __restrict__ Wl,  const float* __restrict__ bl,
    const float* __restrict__ Wl2, const float* __restrict__ bl2)
{
    __shared__ float xs[8 * DD];
    __shared__ float ws[32 * 129];
    __shared__ float ys[8 * DD];
    const int t = threadIdx.x, l0 = blockIdx.x * 8;
    const int dloc = t & 31, lrow = t >> 5;
    for (int i = t; i < 8 * DD; i += 256) xs[i] = x[l0 * DD + i];
    for (int mat = 0; mat < 2; mat++) {
        const float* W    = mat ? Wl2 : Wl;
        const float* bias = mat ? bl2 : bl;
        float*       outp = mat ? g_tx : g_a;
        unsigned*    oh   = mat ? g_bh : g_ah;
        unsigned*    om   = mat ? g_bm : g_am;
        for (int dc = 0; dc < 4; dc++) {
            const int d0 = dc * 32;
            __syncthreads();
            for (int i = t; i < 32 * DD; i += 256) {
                int r = i >> 7, c = i & 127;
                ws[r * 129 + c] = W[(d0 + r) * DD + c];
            }
            __syncthreads();
            float acc = 0.f;
            #pragma unroll 8
            for (int c = 0; c < DD; c++) acc += xs[lrow * DD + c] * ws[dloc * 129 + c];
            acc += bias[d0 + dloc];
            outp[(l0 + lrow) * DD + d0 + dloc] = acc;
            ys[lrow * DD + d0 + dloc] = acc;
        }
        __syncthreads();
        // pack pair-words: rows (2j, 2j+1), j=0..3 -> global kp = l0/2 + j
        #pragma unroll
        for (int i = 0; i < 2; i++) {
            int idx = t + 256 * i;              // 0..511
            int j = idx >> 7, c = idx & 127;
            float x0 = ys[(2 * j) * DD + c];
            float x1 = ys[(2 * j + 1) * DD + c];
            unsigned uh, um; split_bf16(x0, x1, uh, um);
            int kp = (l0 >> 1) + j;
            oh[kp * DD + c] = uh; om[kp * DD + c] = um;
        }
    }
}

// ---------------- kernel 2: mask pair-words + tile counter reset ----------------
__global__ __launch_bounds__(256) void prep_mask_kernel(const int* __restrict__ mask)
{
    const int idx = blockIdx.x * 256 + threadIdx.x;
    if (idx == 0) g_tile_ctr = 0u;
    const int l = idx >> 9, kp = idx & 511;
    int ma = mask[l * LLEN + 2 * kp];
    int mb = mask[l * LLEN + 2 * kp + 1];
    g_mkp[idx] = (ma ? 0x0000FFFFu : 0u) | (mb ? 0xFFFF0000u : 0u);
}

// ---------------- kernel 3: R partials, grid (64 l-tiles, 4 m-groups) ----------------
__global__ __launch_bounds__(256) void r_kernel(const int* __restrict__ mask)
{
    __shared__ float s_txc[64 * DD];
    __shared__ float s_mk [16 * 64];
    const int t = threadIdx.x;
    const int l0 = blockIdx.x * 16;
    const int mg = blockIdx.y;
    const int d4 = t & 31, lg = t >> 5;
    float4 a0 = {0.f,0.f,0.f,0.f}, a1 = {0.f,0.f,0.f,0.f};
    for (int ch = 0; ch < 4; ch++) {
        const int m0 = mg * 256 + ch * 64;
        __syncthreads();
        #pragma unroll
        for (int r = 0; r < 8; r++) {
            int idx = t + 256 * r;
            int rw = idx >> 5, c4 = idx & 31;
            *(float4*)&s_txc[rw * DD + c4 * 4] = *(const float4*)&g_tx[(m0 + rw) * DD + c4 * 4];
        }
        #pragma unroll
        for (int r = 0; r < 4; r++) {
            int idx = t + 256 * r;
            int li = idx >> 6, mm = idx & 63;
            s_mk[li * 64 + mm] = (mask[(l0 + li) * LLEN + m0 + mm] != 0) ? 1.f : 0.f;
        }
        __syncthreads();
        #pragma unroll 4
        for (int mm = 0; mm < 64; mm++) {
            float4 tv = *(float4*)&s_txc[mm * DD + d4 * 4];
            float f0 = s_mk[(lg * 2) * 64 + mm];
            float f1 = s_mk[(lg * 2 + 1) * 64 + mm];
            a0.x += tv.x * f0; a0.y += tv.y * f0; a0.z += tv.z * f0; a0.w += tv.w * f0;
            a1.x += tv.x * f1; a1.y += tv.y * f1; a1.z += tv.z * f1; a1.w += tv.w * f1;
        }
    }
    *(float4*)&g_Rp[(mg * LLEN + l0 + lg * 2) * DD + d4 * 4]     = a0;
    *(float4*)&g_Rp[(mg * LLEN + l0 + lg * 2 + 1) * DD + d4 * 4] = a1;
}

// ---------------- kernel 4: persistent mma.sync GEMM + fused epilogue ----------------
// R4-verified inner structure (8 warps, 256 threads). Persistent tile loop with
// atomic work-stealing over 512 tiles (tile-deterministic output).
// SMEM: s_a 0..2048, s_mk 2048..10240, Ah@10240(8704) Am@18944(8704)
//       Bh@27648(4608) Bm@32256(4608); epilogue: wlo@2048, ep@35840(8192). Total 44032.
__global__ __launch_bounds__(256, 1) void cop_kernel(const float* __restrict__ Wlo)
{
    extern __shared__ char sm[];
    float*    s_a  = (float*)sm;
    unsigned* s_mk = (unsigned*)(sm + 2048);
    unsigned* sAh  = (unsigned*)(sm + 10240);
    unsigned* sAm  = (unsigned*)(sm + 18944);
    unsigned* sBh  = (unsigned*)(sm + 27648);
    unsigned* sBm  = (unsigned*)(sm + 32256);
    float*    s_wlo = (float*)(sm + 2048);
    float*    s_ep  = (float*)(sm + 35840);
    __shared__ int s_tile;

    const int t    = threadIdx.x;
    const int w    = t >> 5;
    const int lane = t & 31;
    const int gid  = lane >> 2;
    const int tig  = lane & 3;
    const int ct0  = w * 16;
    const int kpA0 = t >> 5, c4A = t & 31;
    const int kpB  = t >> 4, c4B = t & 15;
    const unsigned aIdx0 = kpA0 * 32 + c4A;

    for (;;) {
        if (t == 0) s_tile = (int)atomicAdd(&g_tile_ctr, 1u);
        __syncthreads();                 // s_tile visible; also fences prior tile's smem reads
        const int tile = s_tile;
        if (tile >= NTILE) break;
        const int l0 = (tile >> 1) * LP;
        const int d0 = (tile & 1) * 64;

        // stage a_l + all mask pair-words for these 4 l's
        #pragma unroll
        for (int i = 0; i < 2; i++) {
            int idx = t + 256 * i;
            s_a[idx] = g_a[(l0 + (idx >> 7)) * DD + (idx & 127)];
        }
        #pragma unroll
        for (int i = 0; i < 8; i++) {
            int idx = t + 256 * i;
            s_mk[idx] = g_mkp[(l0 + (idx >> 9)) * 512 + (idx & 511)];
        }

        float acc[LP][8][4];
        #pragma unroll
        for (int l = 0; l < LP; l++)
            #pragma unroll
            for (int dg = 0; dg < 8; dg++)
                #pragma unroll
                for (int q = 0; q < 4; q++) acc[l][dg][q] = 0.f;

        const unsigned bIdx = kpB * 32 + (d0 >> 2) + c4B;
        uint4 pAh0, pAh1, pAm0, pAm1, pBh, pBm;
        {
            const uint4* Ah4 = (const uint4*)g_ah; const uint4* Am4 = (const uint4*)g_am;
            const uint4* Bh4 = (const uint4*)g_bh; const uint4* Bm4 = (const uint4*)g_bm;
            pAh0 = Ah4[aIdx0]; pAh1 = Ah4[aIdx0 + 256];
            pAm0 = Am4[aIdx0]; pAm1 = Am4[aIdx0 + 256];
            pBh  = Bh4[bIdx];  pBm  = Bm4[bIdx];
        }

        #pragma unroll 1
        for (int r = 0; r < 32; r++) {
            __syncthreads();
            *(uint4*)&sAh[kpA0 * 136 + c4A * 4]       = pAh0;
            *(uint4*)&sAh[(kpA0 + 8) * 136 + c4A * 4] = pAh1;
            *(uint4*)&sAm[kpA0 * 136 + c4A * 4]       = pAm0;
            *(uint4*)&sAm[(kpA0 + 8) * 136 + c4A * 4] = pAm1;
            *(uint4*)&sBh[kpB * 72 + c4B * 4]         = pBh;
            *(uint4*)&sBm[kpB * 72 + c4B * 4]         = pBm;
            __syncthreads();
            if (r < 31) {
                const unsigned ofs = (unsigned)(r + 1) * 512;
                const uint4* Ah4 = (const uint4*)g_ah; const uint4* Am4 = (const uint4*)g_am;
                const uint4* Bh4 = (const uint4*)g_bh; const uint4* Bm4 = (const uint4*)g_bm;
                pAh0 = Ah4[ofs + aIdx0]; pAh1 = Ah4[ofs + aIdx0 + 256];
                pAm0 = Am4[ofs + aIdx0]; pAm1 = Am4[ofs + aIdx0 + 256];
                pBh  = Bh4[ofs + bIdx];  pBm  = Bm4[ofs + bIdx];
            }
            const int kpg = r * 16;
            #pragma unroll
            for (int s = 0; s < 2; s++) {
                const int kb = 8 * s;
                unsigned ah0 = sAh[(kb + tig) * 136 + ct0 + gid];
                unsigned ah1 = sAh[(kb + tig) * 136 + ct0 + gid + 8];
                unsigned ah2 = sAh[(kb + tig + 4) * 136 + ct0 + gid];
                unsigned ah3 = sAh[(kb + tig + 4) * 136 + ct0 + gid + 8];
                unsigned am0 = sAm[(kb + tig) * 136 + ct0 + gid];
                unsigned am1 = sAm[(kb + tig) * 136 + ct0 + gid + 8];
                unsigned am2 = sAm[(kb + tig + 4) * 136 + ct0 + gid];
                unsigned am3 = sAm[(kb + tig + 4) * 136 + ct0 + gid + 8];
                unsigned mkl[LP], mkh[LP];
                #pragma unroll
                for (int l = 0; l < LP; l++) {
                    mkl[l] = s_mk[l * 512 + kpg + kb + tig];
                    mkh[l] = s_mk[l * 512 + kpg + kb + tig + 4];
                }
                unsigned b0[8], b1[8];
                #pragma unroll
                for (int dg = 0; dg < 8; dg++) {
                    b0[dg] = sBh[(kb + tig) * 72 + dg * 8 + gid];
                    b1[dg] = sBh[(kb + tig + 4) * 72 + dg * 8 + gid];
                }
                #pragma unroll
                for (int l = 0; l < LP; l++) {      // hh
                    unsigned x0 = ah0 & mkl[l], x1 = ah1 & mkl[l];
                    unsigned x2 = ah2 & mkh[l], x3 = ah3 & mkh[l];
                    #pragma unroll
                    for (int dg = 0; dg < 8; dg++)
                        mma_bf16(acc[l][dg], x0, x1, x2, x3, b0[dg], b1[dg]);
                }
                #pragma unroll
                for (int l = 0; l < LP; l++) {      // mh
                    unsigned x0 = am0 & mkl[l], x1 = am1 & mkl[l];
                    unsigned x2 = am2 & mkh[l], x3 = am3 & mkh[l];
                    #pragma unroll
                    for (int dg = 0; dg < 8; dg++)
                        mma_bf16(acc[l][dg], x0, x1, x2, x3, b0[dg], b1[dg]);
                }
                #pragma unroll
                for (int dg = 0; dg < 8; dg++) {
                    b0[dg] = sBm[(kb + tig) * 72 + dg * 8 + gid];
                    b1[dg] = sBm[(kb + tig + 4) * 72 + dg * 8 + gid];
                }
                #pragma unroll
                for (int l = 0; l < LP; l++) {      // hm
                    unsigned x0 = ah0 & mkl[l], x1 = ah1 & mkl[l];
                    unsigned x2 = ah2 & mkh[l], x3 = ah3 & mkh[l];
                    #pragma unroll
                    for (int dg = 0; dg < 8; dg++)
                        mma_bf16(acc[l][dg], x0, x1, x2, x3, b0[dg], b1[dg]);
                }
            }
        }

        // ---- epilogue: sum_c a_l[c]*Wlo[d,c]*H, reduce, write g_o1 ----
        __syncthreads();
        #pragma unroll
        for (int i = 0; i < 32; i++) {
            int idx = t + 256 * i;
            int dd = idx >> 7, c = idx & 127;
            s_wlo[dd * 132 + c] = Wlo[(d0 + dd) * DD + c];
        }
        __syncthreads();

        const int cA = ct0 + gid, cB = cA + 8;
        #pragma unroll
        for (int l = 0; l < LP; l++) {
            const float aA = s_a[l * DD + cA];
            const float aB = s_a[l * DD + cB];
            float pd[16];
            #pragma unroll
            for (int dg = 0; dg < 8; dg++) {
                const int dl0 = dg * 8 + 2 * tig;
                float w0  = s_wlo[dl0 * 132 + cA],  w1  = s_wlo[(dl0 + 1) * 132 + cA];
                float w0b = s_wlo[dl0 * 132 + cB],  w1b = s_wlo[(dl0 + 1) * 132 + cB];
                pd[2 * dg]     = acc[l][dg][0] * (aA * w0) + acc[l][dg][2] * (aB * w0b);
                pd[2 * dg + 1] = acc[l][dg][1] * (aA * w1) + acc[l][dg][3] * (aB * w1b);
            }
            #pragma unroll
            for (int off = 16; off >= 4; off >>= 1)
                #pragma unroll
                for (int q = 0; q < 16; q++)
                    pd[q] += __shfl_down_sync(0xffffffffu, pd[q], off);
            if (lane < 4) {
                #pragma unroll
                for (int dg = 0; dg < 8; dg++) {
                    s_ep[w * 256 + l * 64 + dg * 8 + 2 * lane]     = pd[2 * dg];
                    s_ep[w * 256 + l * 64 + dg * 8 + 2 * lane + 1] = pd[2 * dg + 1];
                }
            }
        }
        __syncthreads();
        {
            const int l = t >> 6, dloc = t & 63;
            float v = s_ep[t] + s_ep[256 + t] + s_ep[512 + t] + s_ep[768 + t]
                    + s_ep[1024 + t] + s_ep[1280 + t] + s_ep[1536 + t] + s_ep[1792 + t];
            g_o1[(l0 + l) * DD + d0 + dloc] = v;
        }
    }
}

// ---------------- kernel 5: residual + blo*R + LayerNorm ----------------
__global__ __launch_bounds__(128) void ln_kernel(
    const float* __restrict__ x,   const float* __restrict__ blo,
    const float* __restrict__ gamma, const float* __restrict__ beta,
    float* __restrict__ out)
{
    __shared__ float w1[4], w2[4];
    __shared__ float mu_s, rstd_s;
    const int l = blockIdx.x;
    const int d = threadIdx.x;
    float Rv = g_Rp[l * DD + d] + g_Rp[(LLEN + l) * DD + d]
             + g_Rp[(2 * LLEN + l) * DD + d] + g_Rp[(3 * LLEN + l) * DD + d];
    float y = x[l * DD + d] + g_o1[l * DD + d] + blo[d] * Rv;
    float s1 = y, s2 = y * y;
    #pragma unroll
    for (int off = 16; off > 0; off >>= 1) {
        s1 += __shfl_down_sync(0xffffffffu, s1, off);
        s2 += __shfl_down_sync(0xffffffffu, s2, off);
    }
    const int wid = d >> 5, lid = d & 31;
    if (lid == 0) { w1[wid] = s1; w2[wid] = s2; }
    __syncthreads();
    if (d == 0) {
        float t1 = w1[0] + w1[1] + w1[2] + w1[3];
        float t2 = w2[0] + w2[1] + w2[2] + w2[3];
        float mu = t1 * (1.f / DD);
        float var = t2 * (1.f / DD) - mu * mu;
        mu_s = mu; rstd_s = rsqrtf(var + EPSF);
    }
    __syncthreads();
    out[l * DD + d] = (y - mu_s) * rstd_s * gamma[d] + beta[d];
}

// ---------------- launch ----------------
extern "C" void kernel_launch(void* const* d_in, const int* in_sizes, int n_in,
                              void* d_out, int out_size)
{
    (void)in_sizes; (void)n_in; (void)out_size;
    const float* x     = (const float*)d_in[0];
    const int*   mask  = (const int*)  d_in[1];
    const float* Wl    = (const float*)d_in[2];
    const float* bl    = (const float*)d_in[3];
    const float* Wlo   = (const float*)d_in[4];
    const float* blo   = (const float*)d_in[5];
    const float* Wl2   = (const float*)d_in[6];
    const float* bl2   = (const float*)d_in[7];
    const float* gamma = (const float*)d_in[8];
    const float* beta  = (const float*)d_in[9];
    float* out = (float*)d_out;

    proj_kernel<<<128, 256>>>(x, Wl, bl, Wl2, bl2);        // 1
    prep_mask_kernel<<<2048, 256>>>(mask);                 // 2
    r_kernel<<<dim3(64, 4), 256>>>(mask);                  // 3
    cop_kernel<<<148, 256, 44032>>>(Wlo);                  // 4
    ln_kernel<<<1024, 128>>>(x, blo, gamma, beta, out);    // 5
}

// round 7
// speedup vs baseline: 2.8682x; 1.0628x over previous
#include <cuda_runtime.h>
#include <cuda_bf16.h>

#define LLEN 1024
#define DD   128
#define EPSF 1e-5f
#define LP   4
#define NTILE 512   // 256 l-tiles x 2 d-halves
#define TBUF 26624  // bytes per tile buffer (Ah+Am+Bh+Bm)

// ---------------- scratch (device globals; no allocation) ----------------
__device__ float    g_a  [LLEN * DD];
__device__ float    g_tx [LLEN * DD];
__device__ float    g_Rp [4 * LLEN * DD];
__device__ float    g_o1 [LLEN * DD];
__device__ unsigned g_ah [512 * DD];
__device__ unsigned g_am [512 * DD];
__device__ unsigned g_bh [512 * DD];
__device__ unsigned g_bm [512 * DD];
__device__ unsigned g_mkp[LLEN * 512];
__device__ unsigned g_tile_ctr;

// ---------------- helpers ----------------
__device__ __forceinline__ unsigned pack_bf16x2(float lo, float hi) {
    unsigned u;
    asm("cvt.rn.bf16x2.f32 %0, %1, %2;" : "=r"(u) : "f"(hi), "f"(lo));
    return u;
}
__device__ __forceinline__ void split_bf16(float x0, float x1, unsigned& uh, unsigned& um) {
    uh = pack_bf16x2(x0, x1);
    float h0 = __uint_as_float(uh << 16);
    float h1 = __uint_as_float(uh & 0xFFFF0000u);
    um = pack_bf16x2(x0 - h0, x1 - h1);
}
__device__ __forceinline__ void mma_bf16(float* c, unsigned a0, unsigned a1, unsigned a2,
                                         unsigned a3, unsigned b0, unsigned b1) {
    asm volatile(
        "mma.sync.aligned.m16n8k16.row.col.f32.bf16.bf16.f32 "
        "{%0,%1,%2,%3}, {%4,%5,%6,%7}, {%8,%9}, {%0,%1,%2,%3};"
        : "+f"(c[0]), "+f"(c[1]), "+f"(c[2]), "+f"(c[3])
        : "r"(a0), "r"(a1), "r"(a2), "r"(a3), "r"(b0), "r"(b1));
}

// ---------------- kernel 1: projections + fused bf16 split ----------------
__global__ __launch_bounds__(256) void proj_kernel(
    const float* __restrict__ x,
    const float* __restrict__ Wl,  const float* __restrict__ bl,
    const float* __restrict__ Wl2, const float* __restrict__ bl2)
{
    __shared__ float xs[8 * DD];
    __shared__ float ws[32 * 129];
    __shared__ float ys[8 * DD];
    const int t = threadIdx.x, l0 = blockIdx.x * 8;
    const int dloc = t & 31, lrow = t >> 5;
    for (int i = t; i < 8 * DD; i += 256) xs[i] = x[l0 * DD + i];
    for (int mat = 0; mat < 2; mat++) {
        const float* W    = mat ? Wl2 : Wl;
        const float* bias = mat ? bl2 : bl;
        float*       outp = mat ? g_tx : g_a;
        unsigned*    oh   = mat ? g_bh : g_ah;
        unsigned*    om   = mat ? g_bm : g_am;
        for (int dc = 0; dc < 4; dc++) {
            const int d0 = dc * 32;
            __syncthreads();
            for (int i = t; i < 32 * DD; i += 256) {
                int r = i >> 7, c = i & 127;
                ws[r * 129 + c] = W[(d0 + r) * DD + c];
            }
            __syncthreads();
            float acc = 0.f;
            #pragma unroll 8
            for (int c = 0; c < DD; c++) acc += xs[lrow * DD + c] * ws[dloc * 129 + c];
            acc += bias[d0 + dloc];
            outp[(l0 + lrow) * DD + d0 + dloc] = acc;
            ys[lrow * DD + d0 + dloc] = acc;
        }
        __syncthreads();
        #pragma unroll
        for (int i = 0; i < 2; i++) {
            int idx = t + 256 * i;
            int j = idx >> 7, c = idx & 127;
            float x0 = ys[(2 * j) * DD + c];
            float x1 = ys[(2 * j + 1) * DD + c];
            unsigned uh, um; split_bf16(x0, x1, uh, um);
            int kp = (l0 >> 1) + j;
            oh[kp * DD + c] = uh; om[kp * DD + c] = um;
        }
    }
}

// ---------------- kernel 2: mask pair-words + tile counter reset ----------------
__global__ __launch_bounds__(256) void prep_mask_kernel(const int* __restrict__ mask)
{
    const int idx = blockIdx.x * 256 + threadIdx.x;
    if (idx == 0) g_tile_ctr = 0u;
    const int l = idx >> 9, kp = idx & 511;
    int ma = mask[l * LLEN + 2 * kp];
    int mb = mask[l * LLEN + 2 * kp + 1];
    g_mkp[idx] = (ma ? 0x0000FFFFu : 0u) | (mb ? 0xFFFF0000u : 0u);
}

// ---------------- kernel 3: R partials ----------------
__global__ __launch_bounds__(256) void r_kernel(const int* __restrict__ mask)
{
    __shared__ float s_txc[64 * DD];
    __shared__ float s_mk [16 * 64];
    const int t = threadIdx.x;
    const int l0 = blockIdx.x * 16;
    const int mg = blockIdx.y;
    const int d4 = t & 31, lg = t >> 5;
    float4 a0 = {0.f,0.f,0.f,0.f}, a1 = {0.f,0.f,0.f,0.f};
    for (int ch = 0; ch < 4; ch++) {
        const int m0 = mg * 256 + ch * 64;
        __syncthreads();
        #pragma unroll
        for (int r = 0; r < 8; r++) {
            int idx = t + 256 * r;
            int rw = idx >> 5, c4 = idx & 31;
            *(float4*)&s_txc[rw * DD + c4 * 4] = *(const float4*)&g_tx[(m0 + rw) * DD + c4 * 4];
        }
        #pragma unroll
        for (int r = 0; r < 4; r++) {
            int idx = t + 256 * r;
            int li = idx >> 6, mm = idx & 63;
            s_mk[li * 64 + mm] = (mask[(l0 + li) * LLEN + m0 + mm] != 0) ? 1.f : 0.f;
        }
        __syncthreads();
        #pragma unroll 4
        for (int mm = 0; mm < 64; mm++) {
            float4 tv = *(float4*)&s_txc[mm * DD + d4 * 4];
            float f0 = s_mk[(lg * 2) * 64 + mm];
            float f1 = s_mk[(lg * 2 + 1) * 64 + mm];
            a0.x += tv.x * f0; a0.y += tv.y * f0; a0.z += tv.z * f0; a0.w += tv.w * f0;
            a1.x += tv.x * f1; a1.y += tv.y * f1; a1.z += tv.z * f1; a1.w += tv.w * f1;
        }
    }
    *(float4*)&g_Rp[(mg * LLEN + l0 + lg * 2) * DD + d4 * 4]     = a0;
    *(float4*)&g_Rp[(mg * LLEN + l0 + lg * 2 + 1) * DD + d4 * 4] = a1;
}

// ---------------- kernel 4: persistent mma.sync GEMM, double-buffered, 1 sync/round ----------------
// SMEM: s_a 0..2048, s_mk 2048..10240,
//   buf0 @10240: Ah(8704) Am(8704) Bh(4608) Bm(4608)  -> 10240..36864
//   buf1 @36864: same                                  -> 36864..63488
// Epilogue reuse: wlo@10240 (33792), ep@50176 (8192). Total dynamic = 63488.
__global__ __launch_bounds__(256, 1) void cop_kernel(const float* __restrict__ Wlo)
{
    extern __shared__ char sm[];
    float*    s_a  = (float*)sm;
    unsigned* s_mk = (unsigned*)(sm + 2048);
    float*    s_wlo = (float*)(sm + 10240);
    float*    s_ep  = (float*)(sm + 50176);
    __shared__ int s_tile;

    const int t    = threadIdx.x;
    const int w    = t >> 5;
    const int lane = t & 31;
    const int gid  = lane >> 2;
    const int tig  = lane & 3;
    const int ct0  = w * 16;
    const int kpA0 = t >> 5, c4A = t & 31;
    const int kpB  = t >> 4, c4B = t & 15;
    const unsigned aIdx0 = kpA0 * 32 + c4A;

    for (;;) {
        if (t == 0) s_tile = (int)atomicAdd(&g_tile_ctr, 1u);
        __syncthreads();
        const int tile = s_tile;
        if (tile >= NTILE) break;
        const int l0 = (tile >> 1) * LP;
        const int d0 = (tile & 1) * 64;

        #pragma unroll
        for (int i = 0; i < 2; i++) {
            int idx = t + 256 * i;
            s_a[idx] = g_a[(l0 + (idx >> 7)) * DD + (idx & 127)];
        }
        #pragma unroll
        for (int i = 0; i < 8; i++) {
            int idx = t + 256 * i;
            s_mk[idx] = g_mkp[(l0 + (idx >> 9)) * 512 + (idx & 511)];
        }

        float acc[LP][8][4];
        #pragma unroll
        for (int l = 0; l < LP; l++)
            #pragma unroll
            for (int dg = 0; dg < 8; dg++)
                #pragma unroll
                for (int q = 0; q < 4; q++) acc[l][dg][q] = 0.f;

        const unsigned bIdx = kpB * 32 + (d0 >> 2) + c4B;
        uint4 pAh0, pAh1, pAm0, pAm1, pBh, pBm;
        {
            const uint4* Ah4 = (const uint4*)g_ah; const uint4* Am4 = (const uint4*)g_am;
            const uint4* Bh4 = (const uint4*)g_bh; const uint4* Bm4 = (const uint4*)g_bm;
            pAh0 = Ah4[aIdx0]; pAh1 = Ah4[aIdx0 + 256];
            pAm0 = Am4[aIdx0]; pAm1 = Am4[aIdx0 + 256];
            pBh  = Bh4[bIdx];  pBm  = Bm4[bIdx];
        }

        #pragma unroll 1
        for (int r = 0; r < 32; r++) {
            char* buf = sm + 10240 + (r & 1) * TBUF;
            unsigned* sAh = (unsigned*)(buf);
            unsigned* sAm = (unsigned*)(buf + 8704);
            unsigned* sBh = (unsigned*)(buf + 17408);
            unsigned* sBm = (unsigned*)(buf + 22016);

            // STS into this round's buffer (safe: last readers were round r-2,
            // separated by the r-1 and r barriers)
            *(uint4*)&sAh[kpA0 * 136 + c4A * 4]       = pAh0;
            *(uint4*)&sAh[(kpA0 + 8) * 136 + c4A * 4] = pAh1;
            *(uint4*)&sAm[kpA0 * 136 + c4A * 4]       = pAm0;
            *(uint4*)&sAm[(kpA0 + 8) * 136 + c4A * 4] = pAm1;
            *(uint4*)&sBh[kpB * 72 + c4B * 4]         = pBh;
            *(uint4*)&sBm[kpB * 72 + c4B * 4]         = pBm;
            __syncthreads();   // publish round-r tiles (r=0: also covers s_a/s_mk staging)

            if (r < 31) {
                const unsigned ofs = (unsigned)(r + 1) * 512;
                const uint4* Ah4 = (const uint4*)g_ah; const uint4* Am4 = (const uint4*)g_am;
                const uint4* Bh4 = (const uint4*)g_bh; const uint4* Bm4 = (const uint4*)g_bm;
                pAh0 = Ah4[ofs + aIdx0]; pAh1 = Ah4[ofs + aIdx0 + 256];
                pAm0 = Am4[ofs + aIdx0]; pAm1 = Am4[ofs + aIdx0 + 256];
                pBh  = Bh4[ofs + bIdx];  pBm  = Bm4[ofs + bIdx];
            }
            const int kpg = r * 16;
            #pragma unroll
            for (int s = 0; s < 2; s++) {
                const int kb = 8 * s;
                unsigned ah0 = sAh[(kb + tig) * 136 + ct0 + gid];
                unsigned ah1 = sAh[(kb + tig) * 136 + ct0 + gid + 8];
                unsigned ah2 = sAh[(kb + tig + 4) * 136 + ct0 + gid];
                unsigned ah3 = sAh[(kb + tig + 4) * 136 + ct0 + gid + 8];
                unsigned am0 = sAm[(kb + tig) * 136 + ct0 + gid];
                unsigned am1 = sAm[(kb + tig) * 136 + ct0 + gid + 8];
                unsigned am2 = sAm[(kb + tig + 4) * 136 + ct0 + gid];
                unsigned am3 = sAm[(kb + tig + 4) * 136 + ct0 + gid + 8];
                unsigned mkl[LP], mkh[LP];
                #pragma unroll
                for (int l = 0; l < LP; l++) {
                    mkl[l] = s_mk[l * 512 + kpg + kb + tig];
                    mkh[l] = s_mk[l * 512 + kpg + kb + tig + 4];
                }
                unsigned b0[8], b1[8];
                #pragma unroll
                for (int dg = 0; dg < 8; dg++) {
                    b0[dg] = sBh[(kb + tig) * 72 + dg * 8 + gid];
                    b1[dg] = sBh[(kb + tig + 4) * 72 + dg * 8 + gid];
                }
                #pragma unroll
                for (int l = 0; l < LP; l++) {      // hh
                    unsigned x0 = ah0 & mkl[l], x1 = ah1 & mkl[l];
                    unsigned x2 = ah2 & mkh[l], x3 = ah3 & mkh[l];
                    #pragma unroll
                    for (int dg = 0; dg < 8; dg++)
                        mma_bf16(acc[l][dg], x0, x1, x2, x3, b0[dg], b1[dg]);
                }
                #pragma unroll
                for (int l = 0; l < LP; l++) {      // mh
                    unsigned x0 = am0 & mkl[l], x1 = am1 & mkl[l];
                    unsigned x2 = am2 & mkh[l], x3 = am3 & mkh[l];
                    #pragma unroll
                    for (int dg = 0; dg < 8; dg++)
                        mma_bf16(acc[l][dg], x0, x1, x2, x3, b0[dg], b1[dg]);
                }
                #pragma unroll
                for (int dg = 0; dg < 8; dg++) {
                    b0[dg] = sBm[(kb + tig) * 72 + dg * 8 + gid];
                    b1[dg] = sBm[(kb + tig + 4) * 72 + dg * 8 + gid];
                }
                #pragma unroll
                for (int l = 0; l < LP; l++) {      // hm
                    unsigned x0 = ah0 & mkl[l], x1 = ah1 & mkl[l];
                    unsigned x2 = ah2 & mkh[l], x3 = ah3 & mkh[l];
                    #pragma unroll
                    for (int dg = 0; dg < 8; dg++)
                        mma_bf16(acc[l][dg], x0, x1, x2, x3, b0[dg], b1[dg]);
                }
            }
        }

        // ---- epilogue ----
        __syncthreads();
        #pragma unroll
        for (int i = 0; i < 32; i++) {
            int idx = t + 256 * i;
            int dd = idx >> 7, c = idx & 127;
            s_wlo[dd * 132 + c] = Wlo[(d0 + dd) * DD + c];
        }
        __syncthreads();

        const int cA = ct0 + gid, cB = cA + 8;
        #pragma unroll
        for (int l = 0; l < LP; l++) {
            const float aA = s_a[l * DD + cA];
            const float aB = s_a[l * DD + cB];
            float pd[16];
            #pragma unroll
            for (int dg = 0; dg < 8; dg++) {
                const int dl0 = dg * 8 + 2 * tig;
                float w0  = s_wlo[dl0 * 132 + cA],  w1  = s_wlo[(dl0 + 1) * 132 + cA];
                float w0b = s_wlo[dl0 * 132 + cB],  w1b = s_wlo[(dl0 + 1) * 132 + cB];
                pd[2 * dg]     = acc[l][dg][0] * (aA * w0) + acc[l][dg][2] * (aB * w0b);
                pd[2 * dg + 1] = acc[l][dg][1] * (aA * w1) + acc[l][dg][3] * (aB * w1b);
            }
            #pragma unroll
            for (int off = 16; off >= 4; off >>= 1)
                #pragma unroll
                for (int q = 0; q < 16; q++)
                    pd[q] += __shfl_down_sync(0xffffffffu, pd[q], off);
            if (lane < 4) {
                #pragma unroll
                for (int dg = 0; dg < 8; dg++) {
                    s_ep[w * 256 + l * 64 + dg * 8 + 2 * lane]     = pd[2 * dg];
                    s_ep[w * 256 + l * 64 + dg * 8 + 2 * lane + 1] = pd[2 * dg + 1];
                }
            }
        }
        __syncthreads();
        {
            const int l = t >> 6, dloc = t & 63;
            float v = s_ep[t] + s_ep[256 + t] + s_ep[512 + t] + s_ep[768 + t]
                    + s_ep[1024 + t] + s_ep[1280 + t] + s_ep[1536 + t] + s_ep[1792 + t];
            g_o1[(l0 + l) * DD + d0 + dloc] = v;
        }
    }
}

// ---------------- kernel 5: residual + blo*R + LayerNorm ----------------
__global__ __launch_bounds__(128) void ln_kernel(
    const float* __restrict__ x,   const float* __restrict__ blo,
    const float* __restrict__ gamma, const float* __restrict__ beta,
    float* __restrict__ out)
{
    __shared__ float w1[4], w2[4];
    __shared__ float mu_s, rstd_s;
    const int l = blockIdx.x;
    const int d = threadIdx.x;
    float Rv = g_Rp[l * DD + d] + g_Rp[(LLEN + l) * DD + d]
             + g_Rp[(2 * LLEN + l) * DD + d] + g_Rp[(3 * LLEN + l) * DD + d];
    float y = x[l * DD + d] + g_o1[l * DD + d] + blo[d] * Rv;
    float s1 = y, s2 = y * y;
    #pragma unroll
    for (int off = 16; off > 0; off >>= 1) {
        s1 += __shfl_down_sync(0xffffffffu, s1, off);
        s2 += __shfl_down_sync(0xffffffffu, s2, off);
    }
    const int wid = d >> 5, lid = d & 31;
    if (lid == 0) { w1[wid] = s1; w2[wid] = s2; }
    __syncthreads();
    if (d == 0) {
        float t1 = w1[0] + w1[1] + w1[2] + w1[3];
        float t2 = w2[0] + w2[1] + w2[2] + w2[3];
        float mu = t1 * (1.f / DD);
        float var = t2 * (1.f / DD) - mu * mu;
        mu_s = mu; rstd_s = rsqrtf(var + EPSF);
    }
    __syncthreads();
    out[l * DD + d] = (y - mu_s) * rstd_s * gamma[d] + beta[d];
}

// ---------------- launch ----------------
extern "C" void kernel_launch(void* const* d_in, const int* in_sizes, int n_in,
                              void* d_out, int out_size)
{
    (void)in_sizes; (void)n_in; (void)out_size;
    const float* x     = (const float*)d_in[0];
    const int*   mask  = (const int*)  d_in[1];
    const float* Wl    = (const float*)d_in[2];
    const float* bl    = (const float*)d_in[3];
    const float* Wlo   = (const float*)d_in[4];
    const float* blo   = (const float*)d_in[5];
    const float* Wl2   = (const float*)d_in[6];
    const float* bl2   = (const float*)d_in[7];
    const float* gamma = (const float*)d_in[8];
    const float* beta  = (const float*)d_in[9];
    float* out = (float*)d_out;

    static int smem_set = 0;
    if (!smem_set) {
        cudaFuncSetAttribute(cop_kernel, cudaFuncAttributeMaxDynamicSharedMemorySize, 63488);
        smem_set = 1;
    }

    proj_kernel<<<128, 256>>>(x, Wl, bl, Wl2, bl2);        // 1
    prep_mask_kernel<<<2048, 256>>>(mask);                 // 2
    r_kernel<<<dim3(64, 4), 256>>>(mask);                  // 3
    cop_kernel<<<148, 256, 63488>>>(Wlo);                  // 4
    ln_kernel<<<1024, 128>>>(x, blo, gamma, beta, out);    // 5
}